// round 10
// baseline (speedup 1.0000x reference)
#include <cuda_runtime.h>
#include <math.h>
#include <stdint.h>

// Problem constants
constexpr int Bb = 2;
constexpr int Ss = 2048;
constexpr int Dd = 768;
constexpr int Hh = 12;
constexpr int DHd = 64;
constexpr int WIN = 128;

// Scratch (device globals; no allocation allowed)
__device__ __align__(16) float g_Q[Bb * Ss * Hh * DHd];
__device__ __align__(16) float g_K[Bb * Ss * Hh * DHd];
__device__ __align__(16) float g_V[Bb * Ss * Hh * DHd];
__device__ __align__(16) float g_Z[Bb * Ss * Hh * DHd];
// tf32-pre-rounded operands
__device__ __align__(16) float g_Aq[Bb * Ss * Dd];
__device__ __align__(16) float g_Ak[Bb * Ss * Dd];
__device__ __align__(16) float g_Av[Bb * Ss * Dd];
__device__ __align__(16) float g_Wq[Hh * Dd * DHd];
__device__ __align__(16) float g_Wk[Hh * Dd * DHd];
__device__ __align__(16) float g_Wv[Hh * Dd * DHd];
__device__ __align__(16) float g_Wo[Hh * DHd * Dd];
// rotary sin/cos table: [pos][freq] -> (sin, cos)
__device__ __align__(16) float2 g_T[Ss * 32];

__device__ __forceinline__ uint32_t f2tf32(float x) {
    uint32_t u;
    asm("cvt.rna.tf32.f32 %0, %1;" : "=r"(u) : "f"(x));
    return u;
}
__device__ __forceinline__ float round_tf32(float x) {
    return __uint_as_float(f2tf32(x));
}
__device__ __forceinline__ void cpa16(uint32_t dst, const void* src) {
    asm volatile("cp.async.cg.shared.global [%0], [%1], 16;"
                 :: "r"(dst), "l"(src) : "memory");
}
#define CP_COMMIT() asm volatile("cp.async.commit_group;" ::: "memory")
#define CP_WAIT1()  asm volatile("cp.async.wait_group 1;" ::: "memory")

#define MMA_TF32(acc, a, b)                                                   \
    asm volatile(                                                             \
        "mma.sync.aligned.m16n8k8.row.col.f32.tf32.tf32.f32 "                 \
        "{%0,%1,%2,%3}, {%4,%5,%6,%7}, {%8,%9}, {%0,%1,%2,%3};\n"             \
        : "+f"((acc)[0]), "+f"((acc)[1]), "+f"((acc)[2]), "+f"((acc)[3])      \
        : "r"((a)[0]), "r"((a)[1]), "r"((a)[2]), "r"((a)[3]),                 \
          "r"((b)[0]), "r"((b)[1]))

// ---------------------------------------------------------------------------
// Pre-rounding kernels + rotary table init.
// ---------------------------------------------------------------------------
__global__ __launch_bounds__(256) void round3_k(
    const float* __restrict__ a, const float* __restrict__ b,
    const float* __restrict__ c,
    float* __restrict__ da, float* __restrict__ db, float* __restrict__ dc)
{
    int idx = blockIdx.x * 256 + threadIdx.x;
    const float* s = (blockIdx.y == 0) ? a : (blockIdx.y == 1) ? b : c;
    float*       d = (blockIdx.y == 0) ? da : (blockIdx.y == 1) ? db : dc;
    float4 v = ((const float4*)s)[idx];
    v.x = round_tf32(v.x); v.y = round_tf32(v.y);
    v.z = round_tf32(v.z); v.w = round_tf32(v.w);
    ((float4*)d)[idx] = v;
}
__global__ __launch_bounds__(256) void round4_k(
    const float* __restrict__ a, const float* __restrict__ b,
    const float* __restrict__ c, const float* __restrict__ e,
    float* __restrict__ da, float* __restrict__ db,
    float* __restrict__ dc, float* __restrict__ de)
{
    int idx = blockIdx.x * 256 + threadIdx.x;
    const float* s = (blockIdx.y == 0) ? a : (blockIdx.y == 1) ? b
                   : (blockIdx.y == 2) ? c : e;
    float*       d = (blockIdx.y == 0) ? da : (blockIdx.y == 1) ? db
                   : (blockIdx.y == 2) ? dc : de;
    float4 v = ((const float4*)s)[idx];
    v.x = round_tf32(v.x); v.y = round_tf32(v.y);
    v.z = round_tf32(v.z); v.w = round_tf32(v.w);
    ((float4*)d)[idx] = v;
}
__global__ __launch_bounds__(256) void table_k(float2* __restrict__ T)
{
    int tid = blockIdx.x * 256 + threadIdx.x;
    int s = tid >> 5;
    int i = tid & 31;
    float inv_freq = expf(-(float)(2 * i) * (1.0f / 64.0f) * 9.210340371976184f);
    float ang = (float)s * inv_freq;
    float sn, cs;
    sincosf(ang, &sn, &cs);
    T[tid] = make_float2(sn, cs);
}

// ---------------------------------------------------------------------------
// tf32 mma GEMM, cp.async 3-stage, BM=128 BN=128 BK=32.
// 512 threads = 16 warps (4m x 4n), warp tile 32x32 -> acc 32 regs/thread,
// __launch_bounds__(512,2) => <=64 regs => 2 CTAs/SM = 32 warps (50% occ).
// ---------------------------------------------------------------------------
constexpr int AW = 36;
constexpr int BWp = 136;
constexpr int SAW = 128 * AW;
constexpr int SBW = 32 * BWp;
constexpr int STW = SAW + SBW;
constexpr int NST = 3;
constexpr int GEMM_SMEM = NST * STW * 4;
constexpr int ITERS = 24;

template <bool HEADB>
__global__ __launch_bounds__(512, 2) void tgemm_k(
    const float* __restrict__ A0, const float* __restrict__ A1, const float* __restrict__ A2,
    const float* __restrict__ Bm0, const float* __restrict__ Bm1, const float* __restrict__ Bm2,
    const float* __restrict__ bias0, const float* __restrict__ bias1, const float* __restrict__ bias2,
    float* __restrict__ C0, float* __restrict__ C1, float* __restrict__ C2,
    int M, int N, int K)
{
    extern __shared__ float smf[];
    const uint32_t smb = (uint32_t)__cvta_generic_to_shared(smf);

    const int z = blockIdx.z;
    const float* A    = (z == 0) ? A0    : (z == 1) ? A1    : A2;
    const float* Bm   = (z == 0) ? Bm0   : (z == 1) ? Bm1   : Bm2;
    const float* bias = (z == 0) ? bias0 : (z == 1) ? bias1 : bias2;
    float*       C    = (z == 0) ? C0    : (z == 1) ? C1    : C2;

    const int t    = threadIdx.x;
    const int m0   = blockIdx.y * 128;
    const int n0   = blockIdx.x * 128;
    const int warp = t >> 5;
    const int lane = t & 31;
    const int wm   = (warp >> 2) * 32;   // 4 warps in m
    const int wn   = (warp & 3) * 32;    // 4 warps in n
    const int group = lane >> 2;
    const int tig   = lane & 3;

    // loader addressing (512 threads, 16B chunks)
    const int ar = t >> 2;           // A row 0..127 (i: +128? no, 1024 chunks/512 = 2)
    const int ac = (t & 3) * 8;      // A col word 0,8,16,24 — need 2 chunks/row? No:
    // A tile 128x32 = 1024 float4; thread does 2: idx = t + i*512
    // B tile 32x128 = 1024 float4; thread does 2.

    auto issue_stage = [&](int s, int k0) {
        const uint32_t abase = smb + (uint32_t)(s * STW) * 4;
        const uint32_t bbase = abase + SAW * 4;
#pragma unroll
        for (int i = 0; i < 2; i++) {
            int idx = t + i * 512;          // 0..1023
            int r   = idx >> 3;             // 0..127
            int c4  = (idx & 7) * 4;        // 0..28
            cpa16(abase + (uint32_t)(r * AW + c4) * 4,
                  &A[(size_t)(m0 + r) * K + k0 + c4]);
        }
#pragma unroll
        for (int i = 0; i < 2; i++) {
            int idx = t + i * 512;          // 0..1023
            int kr  = idx >> 5;             // 0..31
            int col = (idx & 31) * 4;       // 0..124
            const float* src;
            if (HEADB)
                src = Bm + (size_t)((n0 + col) >> 6) * K * 64
                         + (size_t)(k0 + kr) * 64 + (col & 63);
            else
                src = Bm + (size_t)(k0 + kr) * N + n0 + col;
            cpa16(bbase + (uint32_t)(kr * BWp + col) * 4, src);
        }
        CP_COMMIT();
    };

    float acc[2][4][4];
#pragma unroll
    for (int mt = 0; mt < 2; mt++)
#pragma unroll
        for (int nt = 0; nt < 4; nt++)
#pragma unroll
            for (int j = 0; j < 4; j++) acc[mt][nt][j] = 0.0f;

    issue_stage(0, 0);
    issue_stage(1, 32);

    for (int it = 0; it < ITERS; it++) {
        CP_WAIT1();
        __syncthreads();
        if (it + 2 < ITERS) issue_stage((it + 2) % NST, (it + 2) * 32);
        else                CP_COMMIT();

        const float* As = smf + (it % NST) * STW;
        const float* Bs = As + SAW;

#pragma unroll
        for (int kk = 0; kk < 4; kk++) {
            const int k8 = kk * 8;
            uint32_t a[2][4], b[4][2];
#pragma unroll
            for (int mt = 0; mt < 2; mt++) {
                int r = wm + mt * 16 + group;
                a[mt][0] = __float_as_uint(As[r * AW + k8 + tig]);
                a[mt][1] = __float_as_uint(As[(r + 8) * AW + k8 + tig]);
                a[mt][2] = __float_as_uint(As[r * AW + k8 + tig + 4]);
                a[mt][3] = __float_as_uint(As[(r + 8) * AW + k8 + tig + 4]);
            }
#pragma unroll
            for (int nt = 0; nt < 4; nt++) {
                int cc = wn + nt * 8 + group;
                b[nt][0] = __float_as_uint(Bs[(k8 + tig) * BWp + cc]);
                b[nt][1] = __float_as_uint(Bs[(k8 + tig + 4) * BWp + cc]);
            }
#pragma unroll
            for (int mt = 0; mt < 2; mt++)
#pragma unroll
                for (int nt = 0; nt < 4; nt++)
                    MMA_TF32(acc[mt][nt], a[mt], b[nt]);
        }
    }

#pragma unroll
    for (int mt = 0; mt < 2; mt++) {
#pragma unroll
        for (int nt = 0; nt < 4; nt++) {
            int col  = n0 + wn + nt * 8 + tig * 2;
            float bx = bias[col];
            float by = bias[col + 1];
            int r0 = m0 + wm + mt * 16 + group;
            float2 o0 = make_float2(acc[mt][nt][0] + bx, acc[mt][nt][1] + by);
            float2 o1 = make_float2(acc[mt][nt][2] + bx, acc[mt][nt][3] + by);
            *(float2*)&C[(size_t)r0 * N + col]       = o0;
            *(float2*)&C[(size_t)(r0 + 8) * N + col] = o1;
        }
    }
}

// ---------------------------------------------------------------------------
// Tensor-core sliding-window attention (scores + PV via mma tf32).
// (unchanged from round 9)
// ---------------------------------------------------------------------------
constexpr int QSP = 68;
constexpr int VPP = 72;
constexpr int KDP = 200;
constexpr int SCP = 196;
constexpr int OFF_KS = 64 * VPP;
constexpr int ATTN_SMEM = (OFF_KS + 64 * KDP) * 4;

__global__ __launch_bounds__(256) void attn_k(
    const float* __restrict__ Q, const float* __restrict__ K,
    const float* __restrict__ V, const float2* __restrict__ T,
    float* __restrict__ Z)
{
    extern __shared__ float sm[];
    float* Qs = sm;
    float* Vv = sm;
    float* Kd = sm + OFF_KS;
    float* Sc = sm + OFF_KS;

    const int t  = threadIdx.x;
    const int q0 = blockIdx.x * 64;
    const int h  = blockIdx.y;
    const int b  = blockIdx.z;

    const int warp  = t >> 5;
    const int lane  = t & 31;
    const int group = lane >> 2;
    const int tig   = lane & 3;

#pragma unroll
    for (int pass = 0; pass < 2; pass++) {
        int id  = pass * 8 + warp;
        int c4  = (id >> 1) * 4;
        int row = (id & 1) * 32 + lane;
        int qg  = q0 + row;
        const float* src = &Q[(((size_t)(b * Ss + qg)) * Hh + h) * 64];
        float4 x = *(const float4*)&src[c4];
        float4 y = *(const float4*)&src[c4 + 32];
        float xa[4] = {x.x, x.y, x.z, x.w};
        float ya[4] = {y.x, y.y, y.z, y.w};
        float4 lo, hi;
        float* lop = &lo.x; float* hip = &hi.x;
#pragma unroll
        for (int j = 0; j < 4; j++) {
            float2 sc = T[qg * 32 + c4 + j];
            lop[j] = round_tf32(xa[j] * sc.y - ya[j] * sc.x);
            hip[j] = round_tf32(ya[j] * sc.y + xa[j] * sc.x);
        }
        *(float4*)&Qs[row * QSP + c4]      = lo;
        *(float4*)&Qs[row * QSP + c4 + 32] = hi;
    }
#pragma unroll
    for (int pass = 0; pass < 6; pass++) {
        int id  = pass * 8 + warp;
        int kg  = id % 6;
        int c4  = (id / 6) * 4;
        int key = kg * 32 + lane;
        int jg  = q0 - 128 + key;
        float lov[4] = {0.f, 0.f, 0.f, 0.f};
        float hiv[4] = {0.f, 0.f, 0.f, 0.f};
        if (jg >= 0) {
            const float* src = &K[(((size_t)(b * Ss + jg)) * Hh + h) * 64];
            float4 x = *(const float4*)&src[c4];
            float4 y = *(const float4*)&src[c4 + 32];
            float xa[4] = {x.x, x.y, x.z, x.w};
            float ya[4] = {y.x, y.y, y.z, y.w};
#pragma unroll
            for (int j = 0; j < 4; j++) {
                float2 sc = T[jg * 32 + c4 + j];
                lov[j] = round_tf32(xa[j] * sc.y - ya[j] * sc.x);
                hiv[j] = round_tf32(ya[j] * sc.y + xa[j] * sc.x);
            }
        }
#pragma unroll
        for (int j = 0; j < 4; j++) {
            Kd[(c4 + j) * KDP + key]      = lov[j];
            Kd[(c4 + j + 32) * KDP + key] = hiv[j];
        }
    }
    __syncthreads();

    {
        const int wm = (warp >> 2) * 32;
        const int wn = (warp & 3) * 48;
        float acc[2][6][4];
#pragma unroll
        for (int mt = 0; mt < 2; mt++)
#pragma unroll
            for (int nt = 0; nt < 6; nt++)
#pragma unroll
                for (int j = 0; j < 4; j++) acc[mt][nt][j] = 0.0f;

#pragma unroll
        for (int kk = 0; kk < 8; kk++) {
            const int k8 = kk * 8;
            uint32_t a[2][4], bf[6][2];
#pragma unroll
            for (int mt = 0; mt < 2; mt++) {
                int r = wm + mt * 16 + group;
                a[mt][0] = __float_as_uint(Qs[r * QSP + k8 + tig]);
                a[mt][1] = __float_as_uint(Qs[(r + 8) * QSP + k8 + tig]);
                a[mt][2] = __float_as_uint(Qs[r * QSP + k8 + tig + 4]);
                a[mt][3] = __float_as_uint(Qs[(r + 8) * QSP + k8 + tig + 4]);
            }
#pragma unroll
            for (int nt = 0; nt < 6; nt++) {
                int col = wn + nt * 8 + group;
                bf[nt][0] = __float_as_uint(Kd[(k8 + tig) * KDP + col]);
                bf[nt][1] = __float_as_uint(Kd[(k8 + tig + 4) * KDP + col]);
            }
#pragma unroll
            for (int mt = 0; mt < 2; mt++)
#pragma unroll
                for (int nt = 0; nt < 6; nt++)
                    MMA_TF32(acc[mt][nt], a[mt], bf[nt]);
        }
        __syncthreads();

#pragma unroll
        for (int mt = 0; mt < 2; mt++) {
#pragma unroll
            for (int nt = 0; nt < 6; nt++) {
                int col = wn + nt * 8 + tig * 2;
                int jgl = q0 - 128 + col;
#pragma unroll
                for (int hl = 0; hl < 2; hl++) {
                    int r  = wm + mt * 16 + group + hl * 8;
                    int qg = q0 + r;
                    bool ok0 = (jgl >= 0) && (jgl <= qg) && (jgl > qg - WIN);
                    bool ok1 = (jgl + 1 >= 0) && (jgl + 1 <= qg) && (jgl + 1 > qg - WIN);
                    float2 o;
                    o.x = ok0 ? acc[mt][nt][hl * 2 + 0] * 0.125f : -1e30f;
                    o.y = ok1 ? acc[mt][nt][hl * 2 + 1] * 0.125f : -1e30f;
                    *(float2*)&Sc[r * SCP + col] = o;
                }
            }
        }
    }
    __syncthreads();

    {
        int r = t >> 2;
        int p = t & 3;
        float mx = -1e30f;
        for (int jj = p * 48; jj < p * 48 + 48; jj++)
            mx = fmaxf(mx, Sc[r * SCP + jj]);
        mx = fmaxf(mx, __shfl_xor_sync(0xFFFFFFFFu, mx, 1));
        mx = fmaxf(mx, __shfl_xor_sync(0xFFFFFFFFu, mx, 2));
        float sum = 0.0f;
        for (int jj = p * 48; jj < p * 48 + 48; jj++) {
            float e = __expf(Sc[r * SCP + jj] - mx);
            Sc[r * SCP + jj] = e;
            sum += e;
        }
        sum += __shfl_xor_sync(0xFFFFFFFFu, sum, 1);
        sum += __shfl_xor_sync(0xFFFFFFFFu, sum, 2);
        float inv = 1.0f / sum;
        for (int jj = p * 48; jj < p * 48 + 48; jj++)
            Sc[r * SCP + jj] = round_tf32(Sc[r * SCP + jj] * inv);
    }

    {
        const int wm = (warp >> 2) * 32;
        const int wn = (warp & 3) * 16;
        float acc[2][2][4];
#pragma unroll
        for (int mt = 0; mt < 2; mt++)
#pragma unroll
            for (int nt = 0; nt < 2; nt++)
#pragma unroll
                for (int j = 0; j < 4; j++) acc[mt][nt][j] = 0.0f;

        for (int c = 0; c < 3; c++) {
            __syncthreads();
#pragma unroll
            for (int pass = 0; pass < 2; pass++) {
                int id  = pass * 8 + warp;
                int c4  = (id >> 1) * 4;
                int key = (id & 1) * 32 + lane;
                int jg  = q0 - 128 + c * 64 + key;
                float4 v0 = make_float4(0.f, 0.f, 0.f, 0.f);
                float4 v1 = make_float4(0.f, 0.f, 0.f, 0.f);
                if (jg >= 0) {
                    const float* src = &V[(((size_t)(b * Ss + jg)) * Hh + h) * 64];
                    v0 = *(const float4*)&src[c4];
                    v1 = *(const float4*)&src[c4 + 32];
                    v0.x = round_tf32(v0.x); v0.y = round_tf32(v0.y);
                    v0.z = round_tf32(v0.z); v0.w = round_tf32(v0.w);
                    v1.x = round_tf32(v1.x); v1.y = round_tf32(v1.y);
                    v1.z = round_tf32(v1.z); v1.w = round_tf32(v1.w);
                }
                *(float4*)&Vv[key * VPP + c4]      = v0;
                *(float4*)&Vv[key * VPP + c4 + 32] = v1;
            }
            __syncthreads();

#pragma unroll
            for (int kk = 0; kk < 8; kk++) {
                const int k8 = kk * 8;
                uint32_t a[2][4], bf[2][2];
#pragma unroll
                for (int mt = 0; mt < 2; mt++) {
                    int r = wm + mt * 16 + group;
                    int scol = c * 64 + k8 + tig;
                    a[mt][0] = __float_as_uint(Sc[r * SCP + scol]);
                    a[mt][1] = __float_as_uint(Sc[(r + 8) * SCP + scol]);
                    a[mt][2] = __float_as_uint(Sc[r * SCP + scol + 4]);
                    a[mt][3] = __float_as_uint(Sc[(r + 8) * SCP + scol + 4]);
                }
#pragma unroll
                for (int nt = 0; nt < 2; nt++) {
                    int dcol = wn + nt * 8 + group;
                    bf[nt][0] = __float_as_uint(Vv[(k8 + tig) * VPP + dcol]);
                    bf[nt][1] = __float_as_uint(Vv[(k8 + tig + 4) * VPP + dcol]);
                }
#pragma unroll
                for (int mt = 0; mt < 2; mt++)
#pragma unroll
                    for (int nt = 0; nt < 2; nt++)
                        MMA_TF32(acc[mt][nt], a[mt], bf[nt]);
            }
        }

#pragma unroll
        for (int mt = 0; mt < 2; mt++) {
#pragma unroll
            for (int nt = 0; nt < 2; nt++) {
                int col = wn + nt * 8 + tig * 2;
#pragma unroll
                for (int hl = 0; hl < 2; hl++) {
                    int r = wm + mt * 16 + group + hl * 8;
                    float2 o;
                    o.x = round_tf32(acc[mt][nt][hl * 2 + 0]);
                    o.y = round_tf32(acc[mt][nt][hl * 2 + 1]);
                    *(float2*)&Z[(((size_t)(b * Ss + q0 + r)) * Hh + h) * 64 + col] = o;
                }
            }
        }
    }
}

// ---------------------------------------------------------------------------
extern "C" void kernel_launch(void* const* d_in, const int* in_sizes, int n_in,
                              void* d_out, int out_size)
{
    const float* qin = (const float*)d_in[0];
    const float* kin = (const float*)d_in[1];
    const float* vin = (const float*)d_in[2];
    const float* WQ  = (const float*)d_in[3];
    const float* WK  = (const float*)d_in[4];
    const float* WV  = (const float*)d_in[5];
    const float* WO  = (const float*)d_in[6];
    const float* bQ  = (const float*)d_in[7];
    const float* bK  = (const float*)d_in[8];
    const float* bV  = (const float*)d_in[9];
    const float* bO  = (const float*)d_in[10];
    float* out = (float*)d_out;

    float *pQ, *pK, *pV, *pZ;
    float *pAq, *pAk, *pAv, *pWq, *pWk, *pWv, *pWo;
    float2* pT;
    cudaGetSymbolAddress((void**)&pQ, g_Q);
    cudaGetSymbolAddress((void**)&pK, g_K);
    cudaGetSymbolAddress((void**)&pV, g_V);
    cudaGetSymbolAddress((void**)&pZ, g_Z);
    cudaGetSymbolAddress((void**)&pAq, g_Aq);
    cudaGetSymbolAddress((void**)&pAk, g_Ak);
    cudaGetSymbolAddress((void**)&pAv, g_Av);
    cudaGetSymbolAddress((void**)&pWq, g_Wq);
    cudaGetSymbolAddress((void**)&pWk, g_Wk);
    cudaGetSymbolAddress((void**)&pWv, g_Wv);
    cudaGetSymbolAddress((void**)&pWo, g_Wo);
    cudaGetSymbolAddress((void**)&pT, g_T);

    const int M = Bb * Ss;       // 4096
    const int N = Hh * DHd;      // 768
    const int Kd = Dd;           // 768

    cudaFuncSetAttribute(tgemm_k<true>,
                         cudaFuncAttributeMaxDynamicSharedMemorySize, GEMM_SMEM);
    cudaFuncSetAttribute(tgemm_k<false>,
                         cudaFuncAttributeMaxDynamicSharedMemorySize, GEMM_SMEM);
    cudaFuncSetAttribute(attn_k,
                         cudaFuncAttributeMaxDynamicSharedMemorySize, ATTN_SMEM);

    // Pre-round GEMM operands + rotary table
    round3_k<<<dim3(3072, 3), 256>>>(qin, kin, vin, pAq, pAk, pAv);
    round4_k<<<dim3(576, 4), 256>>>(WQ, WK, WV, WO, pWq, pWk, pWv, pWo);
    table_k<<<Ss * 32 / 256, 256>>>(pT);

    // Fused QKV projections (512-thread blocks)
    tgemm_k<true><<<dim3(N / 128, M / 128, 3), 512, GEMM_SMEM>>>(
        pAq, pAk, pAv, pWq, pWk, pWv, bQ, bK, bV, pQ, pK, pV, M, N, Kd);

    // Attention (rotary fused; scores+PV on tensor cores)
    attn_k<<<dim3(Ss / 64, Hh, Bb), 256, ATTN_SMEM>>>(pQ, pK, pV, pT, pZ);

    // Output projection
    tgemm_k<false><<<dim3(N / 128, M / 128, 1), 512, GEMM_SMEM>>>(
        pZ, pZ, pZ, pWo, pWo, pWo, bO, bO, bO, out, out, out, M, N, Kd);
}

// round 11
// speedup vs baseline: 1.1905x; 1.1905x over previous
#include <cuda_runtime.h>
#include <math.h>
#include <stdint.h>

// Problem constants
constexpr int Bb = 2;
constexpr int Ss = 2048;
constexpr int Dd = 768;
constexpr int Hh = 12;
constexpr int DHd = 64;
constexpr int WIN = 128;

// Scratch (device globals; no allocation allowed)
// Q/K/V/Z are HEAD-MAJOR: [b][h][s][d], plane stride Ss*64 = 131072 = 1<<17
__device__ __align__(16) float g_Q[Bb * Hh * Ss * DHd];
__device__ __align__(16) float g_K[Bb * Hh * Ss * DHd];
__device__ __align__(16) float g_V[Bb * Hh * Ss * DHd];
__device__ __align__(16) float g_Z[Bb * Hh * Ss * DHd];
// tf32-pre-rounded operands
__device__ __align__(16) float g_Aq[Bb * Ss * Dd];
__device__ __align__(16) float g_Ak[Bb * Ss * Dd];
__device__ __align__(16) float g_Av[Bb * Ss * Dd];
__device__ __align__(16) float g_Wq[Hh * Dd * DHd];
__device__ __align__(16) float g_Wk[Hh * Dd * DHd];
__device__ __align__(16) float g_Wv[Hh * Dd * DHd];
__device__ __align__(16) float g_Wo[Hh * DHd * Dd];
// rotary sin/cos table: [pos][freq] -> (sin, cos)
__device__ __align__(16) float2 g_T[Ss * 32];

__device__ __forceinline__ uint32_t f2tf32(float x) {
    uint32_t u;
    asm("cvt.rna.tf32.f32 %0, %1;" : "=r"(u) : "f"(x));
    return u;
}
__device__ __forceinline__ float round_tf32(float x) {
    return __uint_as_float(f2tf32(x));
}
__device__ __forceinline__ void cpa16(uint32_t dst, const void* src) {
    asm volatile("cp.async.cg.shared.global [%0], [%1], 16;"
                 :: "r"(dst), "l"(src) : "memory");
}
#define CP_COMMIT() asm volatile("cp.async.commit_group;" ::: "memory")
#define CP_WAIT1()  asm volatile("cp.async.wait_group 1;" ::: "memory")

#define MMA_TF32(acc, a, b)                                                   \
    asm volatile(                                                             \
        "mma.sync.aligned.m16n8k8.row.col.f32.tf32.tf32.f32 "                 \
        "{%0,%1,%2,%3}, {%4,%5,%6,%7}, {%8,%9}, {%0,%1,%2,%3};\n"             \
        : "+f"((acc)[0]), "+f"((acc)[1]), "+f"((acc)[2]), "+f"((acc)[3])      \
        : "r"((a)[0]), "r"((a)[1]), "r"((a)[2]), "r"((a)[3]),                 \
          "r"((b)[0]), "r"((b)[1]))

// ---------------------------------------------------------------------------
// Pre-rounding kernels + rotary table init.
// ---------------------------------------------------------------------------
__global__ __launch_bounds__(256) void round3_k(
    const float* __restrict__ a, const float* __restrict__ b,
    const float* __restrict__ c,
    float* __restrict__ da, float* __restrict__ db, float* __restrict__ dc)
{
    int idx = blockIdx.x * 256 + threadIdx.x;
    const float* s = (blockIdx.y == 0) ? a : (blockIdx.y == 1) ? b : c;
    float*       d = (blockIdx.y == 0) ? da : (blockIdx.y == 1) ? db : dc;
    float4 v = ((const float4*)s)[idx];
    v.x = round_tf32(v.x); v.y = round_tf32(v.y);
    v.z = round_tf32(v.z); v.w = round_tf32(v.w);
    ((float4*)d)[idx] = v;
}
__global__ __launch_bounds__(256) void round4_k(
    const float* __restrict__ a, const float* __restrict__ b,
    const float* __restrict__ c, const float* __restrict__ e,
    float* __restrict__ da, float* __restrict__ db,
    float* __restrict__ dc, float* __restrict__ de)
{
    int idx = blockIdx.x * 256 + threadIdx.x;
    const float* s = (blockIdx.y == 0) ? a : (blockIdx.y == 1) ? b
                   : (blockIdx.y == 2) ? c : e;
    float*       d = (blockIdx.y == 0) ? da : (blockIdx.y == 1) ? db
                   : (blockIdx.y == 2) ? dc : de;
    float4 v = ((const float4*)s)[idx];
    v.x = round_tf32(v.x); v.y = round_tf32(v.y);
    v.z = round_tf32(v.z); v.w = round_tf32(v.w);
    ((float4*)d)[idx] = v;
}
__global__ __launch_bounds__(256) void table_k(float2* __restrict__ T)
{
    int tid = blockIdx.x * 256 + threadIdx.x;
    int s = tid >> 5;
    int i = tid & 31;
    float inv_freq = expf(-(float)(2 * i) * (1.0f / 64.0f) * 9.210340371976184f);
    float ang = (float)s * inv_freq;
    float sn, cs;
    sincosf(ang, &sn, &cs);
    T[tid] = make_float2(sn, cs);
}

// ---------------------------------------------------------------------------
// tf32 mma GEMM, cp.async 3-stage, BM=128 BN=128 BK=32, 256 thr = 8 warps
// (2m x 4n, warp tile 64x32 — the round-8 config, tensor=51%).
// HEADB=true  (QKV): A row-major, B head-blocked (H,K,64), C stored
//                    HEAD-MAJOR [b][h][s][d].
// HEADB=false (WO) : A gathered from head-major Z, B row-major, C row-major.
// ---------------------------------------------------------------------------
constexpr int AW = 36;
constexpr int BWp = 136;
constexpr int SAW = 128 * AW;
constexpr int SBW = 32 * BWp;
constexpr int STW = SAW + SBW;
constexpr int NST = 3;
constexpr int GEMM_SMEM = NST * STW * 4;
constexpr int ITERS = 24;

template <bool HEADB>
__global__ __launch_bounds__(256, 2) void tgemm_k(
    const float* __restrict__ A0, const float* __restrict__ A1, const float* __restrict__ A2,
    const float* __restrict__ Bm0, const float* __restrict__ Bm1, const float* __restrict__ Bm2,
    const float* __restrict__ bias0, const float* __restrict__ bias1, const float* __restrict__ bias2,
    float* __restrict__ C0, float* __restrict__ C1, float* __restrict__ C2,
    int M, int N, int K)
{
    extern __shared__ float smf[];
    const uint32_t smb = (uint32_t)__cvta_generic_to_shared(smf);

    const int z = blockIdx.z;
    const float* A    = (z == 0) ? A0    : (z == 1) ? A1    : A2;
    const float* Bm   = (z == 0) ? Bm0   : (z == 1) ? Bm1   : Bm2;
    const float* bias = (z == 0) ? bias0 : (z == 1) ? bias1 : bias2;
    float*       C    = (z == 0) ? C0    : (z == 1) ? C1    : C2;

    const int t    = threadIdx.x;
    const int m0   = blockIdx.y * 128;
    const int n0   = blockIdx.x * 128;
    const int warp = t >> 5;
    const int lane = t & 31;
    const int wm   = (warp >> 2) * 64;
    const int wn   = (warp & 3) * 32;
    const int group = lane >> 2;
    const int tig   = lane & 3;

    const int ar = t >> 3;
    const int ac = (t & 7) * 4;
    const int br = t >> 3;
    const int bc = (t & 7) * 4;

    auto issue_stage = [&](int s, int k0) {
        const uint32_t abase = smb + (uint32_t)(s * STW) * 4;
        const uint32_t bbase = abase + SAW * 4;
#pragma unroll
        for (int i = 0; i < 4; i++) {
            int r = ar + i * 32;
            const float* asrc;
            if (HEADB) {
                asrc = &A[(size_t)(m0 + r) * K + k0 + ac];
            } else {
                // A = head-major Z: m=(b,s), k=(h,d); k%64 = (k0%64)+ac <= 60
                int m  = m0 + r;
                int b2 = m >> 11, s2 = m & 2047;
                int k  = k0 + ac;
                int h2 = k >> 6,  d2 = k & 63;
                asrc = &A[(((size_t)(b2 * Hh + h2)) << 17) + s2 * 64 + d2];
            }
            cpa16(abase + (uint32_t)(r * AW + ac) * 4, asrc);
        }
#pragma unroll
        for (int j = 0; j < 4; j++) {
            int col = bc + j * 32;
            const float* src;
            if (HEADB)
                src = Bm + (size_t)((n0 + col) >> 6) * K * 64
                         + (size_t)(k0 + br) * 64 + (col & 63);
            else
                src = Bm + (size_t)(k0 + br) * N + n0 + col;
            cpa16(bbase + (uint32_t)(br * BWp + col) * 4, src);
        }
        CP_COMMIT();
    };

    float acc[4][4][4];
#pragma unroll
    for (int mt = 0; mt < 4; mt++)
#pragma unroll
        for (int nt = 0; nt < 4; nt++)
#pragma unroll
            for (int j = 0; j < 4; j++) acc[mt][nt][j] = 0.0f;

    issue_stage(0, 0);
    issue_stage(1, 32);

    for (int it = 0; it < ITERS; it++) {
        CP_WAIT1();
        __syncthreads();
        if (it + 2 < ITERS) issue_stage((it + 2) % NST, (it + 2) * 32);
        else                CP_COMMIT();

        const float* As = smf + (it % NST) * STW;
        const float* Bs = As + SAW;

#pragma unroll
        for (int kk = 0; kk < 4; kk++) {
            const int k8 = kk * 8;
            uint32_t a[4][4], b[4][2];
#pragma unroll
            for (int mt = 0; mt < 4; mt++) {
                int r = wm + mt * 16 + group;
                a[mt][0] = __float_as_uint(As[r * AW + k8 + tig]);
                a[mt][1] = __float_as_uint(As[(r + 8) * AW + k8 + tig]);
                a[mt][2] = __float_as_uint(As[r * AW + k8 + tig + 4]);
                a[mt][3] = __float_as_uint(As[(r + 8) * AW + k8 + tig + 4]);
            }
#pragma unroll
            for (int nt = 0; nt < 4; nt++) {
                int cc = wn + nt * 8 + group;
                b[nt][0] = __float_as_uint(Bs[(k8 + tig) * BWp + cc]);
                b[nt][1] = __float_as_uint(Bs[(k8 + tig + 4) * BWp + cc]);
            }
#pragma unroll
            for (int mt = 0; mt < 4; mt++)
#pragma unroll
                for (int nt = 0; nt < 4; nt++)
                    MMA_TF32(acc[mt][nt], a[mt], b[nt]);
        }
    }

#pragma unroll
    for (int mt = 0; mt < 4; mt++) {
#pragma unroll
        for (int nt = 0; nt < 4; nt++) {
            int col  = n0 + wn + nt * 8 + tig * 2;
            float bx = bias[col];
            float by = bias[col + 1];
            int r0 = m0 + wm + mt * 16 + group;
            float2 o0 = make_float2(acc[mt][nt][0] + bx, acc[mt][nt][1] + by);
            float2 o1 = make_float2(acc[mt][nt][2] + bx, acc[mt][nt][3] + by);
            if (HEADB) {
                // head-major store: rows r0, r0+8 share (b, h)
                int b2 = r0 >> 11, s2 = r0 & 2047;
                int h2 = col >> 6, d2 = col & 63;
                float* dst = &C[(((size_t)(b2 * Hh + h2)) << 17) + s2 * 64 + d2];
                *(float2*)dst         = o0;
                *(float2*)(dst + 512) = o1;   // s2+8 -> +8*64 floats
            } else {
                *(float2*)&C[(size_t)r0 * N + col]       = o0;
                *(float2*)&C[(size_t)(r0 + 8) * N + col] = o1;
            }
        }
    }
}

// ---------------------------------------------------------------------------
// Tensor-core sliding-window attention; Q/K/V/Z HEAD-MAJOR (coalesced tiles).
// ---------------------------------------------------------------------------
constexpr int QSP = 68;
constexpr int VPP = 72;
constexpr int KDP = 200;
constexpr int SCP = 196;
constexpr int OFF_KS = 64 * VPP;
constexpr int ATTN_SMEM = (OFF_KS + 64 * KDP) * 4;

__global__ __launch_bounds__(256) void attn_k(
    const float* __restrict__ Q, const float* __restrict__ K,
    const float* __restrict__ V, const float2* __restrict__ T,
    float* __restrict__ Z)
{
    extern __shared__ float sm[];
    float* Qs = sm;
    float* Vv = sm;
    float* Kd = sm + OFF_KS;
    float* Sc = sm + OFF_KS;

    const int t  = threadIdx.x;
    const int q0 = blockIdx.x * 64;
    const int h  = blockIdx.y;
    const int b  = blockIdx.z;

    const int warp  = t >> 5;
    const int lane  = t & 31;
    const int group = lane >> 2;
    const int tig   = lane & 3;

    const size_t plane = ((size_t)(b * Hh + h)) << 17;   // *131072
    const float* Qh = Q + plane;
    const float* Kh = K + plane;
    const float* Vh = V + plane;
    float*       Zh = Z + plane;

    // ---- Q loader: contiguous rows, rotated + tf32-rounded, q-major ----
#pragma unroll
    for (int i = 0; i < 2; i++) {
        int idx = t + i * 256;          // 0..511
        int row = idx >> 3;             // 0..63
        int c4  = (idx & 7) * 4;        // 0..28
        int qg  = q0 + row;
        const float* src = Qh + (size_t)qg * 64;
        float4 x = *(const float4*)&src[c4];
        float4 y = *(const float4*)&src[c4 + 32];
        float xa[4] = {x.x, x.y, x.z, x.w};
        float ya[4] = {y.x, y.y, y.z, y.w};
        float4 lo, hi;
        float* lop = &lo.x; float* hip = &hi.x;
#pragma unroll
        for (int j = 0; j < 4; j++) {
            float2 sc = T[qg * 32 + c4 + j];
            lop[j] = round_tf32(xa[j] * sc.y - ya[j] * sc.x);
            hip[j] = round_tf32(ya[j] * sc.y + xa[j] * sc.x);
        }
        *(float4*)&Qs[row * QSP + c4]      = lo;
        *(float4*)&Qs[row * QSP + c4 + 32] = hi;
    }
    // ---- K loader: 192 contiguous keys, rotated + rounded, d-major ----
#pragma unroll
    for (int i = 0; i < 6; i++) {
        int idx = t + i * 256;          // 0..1535
        int key = idx >> 3;             // 0..191
        int c4  = (idx & 7) * 4;
        int jg  = q0 - 128 + key;
        float lov[4] = {0.f, 0.f, 0.f, 0.f};
        float hiv[4] = {0.f, 0.f, 0.f, 0.f};
        if (jg >= 0) {
            const float* src = Kh + (size_t)jg * 64;
            float4 x = *(const float4*)&src[c4];
            float4 y = *(const float4*)&src[c4 + 32];
            float xa[4] = {x.x, x.y, x.z, x.w};
            float ya[4] = {y.x, y.y, y.z, y.w};
#pragma unroll
            for (int j = 0; j < 4; j++) {
                float2 sc = T[jg * 32 + c4 + j];
                lov[j] = round_tf32(xa[j] * sc.y - ya[j] * sc.x);
                hiv[j] = round_tf32(ya[j] * sc.y + xa[j] * sc.x);
            }
        }
#pragma unroll
        for (int j = 0; j < 4; j++) {
            Kd[(c4 + j) * KDP + key]      = lov[j];
            Kd[(c4 + j + 32) * KDP + key] = hiv[j];
        }
    }
    __syncthreads();

    // ---- scores mma: warp tile 32q x 48key (2m x 4n warps), K=64 ----
    {
        const int wm = (warp >> 2) * 32;
        const int wn = (warp & 3) * 48;
        float acc[2][6][4];
#pragma unroll
        for (int mt = 0; mt < 2; mt++)
#pragma unroll
            for (int nt = 0; nt < 6; nt++)
#pragma unroll
                for (int j = 0; j < 4; j++) acc[mt][nt][j] = 0.0f;

#pragma unroll
        for (int kk = 0; kk < 8; kk++) {
            const int k8 = kk * 8;
            uint32_t a[2][4], bf[6][2];
#pragma unroll
            for (int mt = 0; mt < 2; mt++) {
                int r = wm + mt * 16 + group;
                a[mt][0] = __float_as_uint(Qs[r * QSP + k8 + tig]);
                a[mt][1] = __float_as_uint(Qs[(r + 8) * QSP + k8 + tig]);
                a[mt][2] = __float_as_uint(Qs[r * QSP + k8 + tig + 4]);
                a[mt][3] = __float_as_uint(Qs[(r + 8) * QSP + k8 + tig + 4]);
            }
#pragma unroll
            for (int nt = 0; nt < 6; nt++) {
                int col = wn + nt * 8 + group;
                bf[nt][0] = __float_as_uint(Kd[(k8 + tig) * KDP + col]);
                bf[nt][1] = __float_as_uint(Kd[(k8 + tig + 4) * KDP + col]);
            }
#pragma unroll
            for (int mt = 0; mt < 2; mt++)
#pragma unroll
                for (int nt = 0; nt < 6; nt++)
                    MMA_TF32(acc[mt][nt], a[mt], bf[nt]);
        }
        __syncthreads();

#pragma unroll
        for (int mt = 0; mt < 2; mt++) {
#pragma unroll
            for (int nt = 0; nt < 6; nt++) {
                int col = wn + nt * 8 + tig * 2;
                int jgl = q0 - 128 + col;
#pragma unroll
                for (int hl = 0; hl < 2; hl++) {
                    int r  = wm + mt * 16 + group + hl * 8;
                    int qg = q0 + r;
                    bool ok0 = (jgl >= 0) && (jgl <= qg) && (jgl > qg - WIN);
                    bool ok1 = (jgl + 1 >= 0) && (jgl + 1 <= qg) && (jgl + 1 > qg - WIN);
                    float2 o;
                    o.x = ok0 ? acc[mt][nt][hl * 2 + 0] * 0.125f : -1e30f;
                    o.y = ok1 ? acc[mt][nt][hl * 2 + 1] * 0.125f : -1e30f;
                    *(float2*)&Sc[r * SCP + col] = o;
                }
            }
        }
    }
    __syncthreads();

    // ---- softmax ----
    {
        int r = t >> 2;
        int p = t & 3;
        float mx = -1e30f;
        for (int jj = p * 48; jj < p * 48 + 48; jj++)
            mx = fmaxf(mx, Sc[r * SCP + jj]);
        mx = fmaxf(mx, __shfl_xor_sync(0xFFFFFFFFu, mx, 1));
        mx = fmaxf(mx, __shfl_xor_sync(0xFFFFFFFFu, mx, 2));
        float sum = 0.0f;
        for (int jj = p * 48; jj < p * 48 + 48; jj++) {
            float e = __expf(Sc[r * SCP + jj] - mx);
            Sc[r * SCP + jj] = e;
            sum += e;
        }
        sum += __shfl_xor_sync(0xFFFFFFFFu, sum, 1);
        sum += __shfl_xor_sync(0xFFFFFFFFu, sum, 2);
        float inv = 1.0f / sum;
        for (int jj = p * 48; jj < p * 48 + 48; jj++)
            Sc[r * SCP + jj] = round_tf32(Sc[r * SCP + jj] * inv);
    }

    // ---- PV mma: warp tile 32q x 16d, K=192 in 3 chunks ----
    {
        const int wm = (warp >> 2) * 32;
        const int wn = (warp & 3) * 16;
        float acc[2][2][4];
#pragma unroll
        for (int mt = 0; mt < 2; mt++)
#pragma unroll
            for (int nt = 0; nt < 2; nt++)
#pragma unroll
                for (int j = 0; j < 4; j++) acc[mt][nt][j] = 0.0f;

        for (int c = 0; c < 3; c++) {
            __syncthreads();
            // V chunk loader: contiguous 64 keys
#pragma unroll
            for (int i = 0; i < 2; i++) {
                int idx = t + i * 256;
                int key = idx >> 3;         // 0..63
                int c4  = (idx & 7) * 4;
                int jg  = q0 - 128 + c * 64 + key;
                float4 v0 = make_float4(0.f, 0.f, 0.f, 0.f);
                float4 v1 = make_float4(0.f, 0.f, 0.f, 0.f);
                if (jg >= 0) {
                    const float* src = Vh + (size_t)jg * 64;
                    v0 = *(const float4*)&src[c4];
                    v1 = *(const float4*)&src[c4 + 32];
                    v0.x = round_tf32(v0.x); v0.y = round_tf32(v0.y);
                    v0.z = round_tf32(v0.z); v0.w = round_tf32(v0.w);
                    v1.x = round_tf32(v1.x); v1.y = round_tf32(v1.y);
                    v1.z = round_tf32(v1.z); v1.w = round_tf32(v1.w);
                }
                *(float4*)&Vv[key * VPP + c4]      = v0;
                *(float4*)&Vv[key * VPP + c4 + 32] = v1;
            }
            __syncthreads();

#pragma unroll
            for (int kk = 0; kk < 8; kk++) {
                const int k8 = kk * 8;
                uint32_t a[2][4], bf[2][2];
#pragma unroll
                for (int mt = 0; mt < 2; mt++) {
                    int r = wm + mt * 16 + group;
                    int scol = c * 64 + k8 + tig;
                    a[mt][0] = __float_as_uint(Sc[r * SCP + scol]);
                    a[mt][1] = __float_as_uint(Sc[(r + 8) * SCP + scol]);
                    a[mt][2] = __float_as_uint(Sc[r * SCP + scol + 4]);
                    a[mt][3] = __float_as_uint(Sc[(r + 8) * SCP + scol + 4]);
                }
#pragma unroll
                for (int nt = 0; nt < 2; nt++) {
                    int dcol = wn + nt * 8 + group;
                    bf[nt][0] = __float_as_uint(Vv[(k8 + tig) * VPP + dcol]);
                    bf[nt][1] = __float_as_uint(Vv[(k8 + tig + 4) * VPP + dcol]);
                }
#pragma unroll
                for (int mt = 0; mt < 2; mt++)
#pragma unroll
                    for (int nt = 0; nt < 2; nt++)
                        MMA_TF32(acc[mt][nt], a[mt], bf[nt]);
            }
        }

        // epilogue -> Z (head-major, tf32-rounded)
#pragma unroll
        for (int mt = 0; mt < 2; mt++) {
#pragma unroll
            for (int nt = 0; nt < 2; nt++) {
                int col = wn + nt * 8 + tig * 2;
#pragma unroll
                for (int hl = 0; hl < 2; hl++) {
                    int r = wm + mt * 16 + group + hl * 8;
                    float2 o;
                    o.x = round_tf32(acc[mt][nt][hl * 2 + 0]);
                    o.y = round_tf32(acc[mt][nt][hl * 2 + 1]);
                    *(float2*)&Zh[(size_t)(q0 + r) * 64 + col] = o;
                }
            }
        }
    }
}

// ---------------------------------------------------------------------------
extern "C" void kernel_launch(void* const* d_in, const int* in_sizes, int n_in,
                              void* d_out, int out_size)
{
    const float* qin = (const float*)d_in[0];
    const float* kin = (const float*)d_in[1];
    const float* vin = (const float*)d_in[2];
    const float* WQ  = (const float*)d_in[3];
    const float* WK  = (const float*)d_in[4];
    const float* WV  = (const float*)d_in[5];
    const float* WO  = (const float*)d_in[6];
    const float* bQ  = (const float*)d_in[7];
    const float* bK  = (const float*)d_in[8];
    const float* bV  = (const float*)d_in[9];
    const float* bO  = (const float*)d_in[10];
    float* out = (float*)d_out;

    float *pQ, *pK, *pV, *pZ;
    float *pAq, *pAk, *pAv, *pWq, *pWk, *pWv, *pWo;
    float2* pT;
    cudaGetSymbolAddress((void**)&pQ, g_Q);
    cudaGetSymbolAddress((void**)&pK, g_K);
    cudaGetSymbolAddress((void**)&pV, g_V);
    cudaGetSymbolAddress((void**)&pZ, g_Z);
    cudaGetSymbolAddress((void**)&pAq, g_Aq);
    cudaGetSymbolAddress((void**)&pAk, g_Ak);
    cudaGetSymbolAddress((void**)&pAv, g_Av);
    cudaGetSymbolAddress((void**)&pWq, g_Wq);
    cudaGetSymbolAddress((void**)&pWk, g_Wk);
    cudaGetSymbolAddress((void**)&pWv, g_Wv);
    cudaGetSymbolAddress((void**)&pWo, g_Wo);
    cudaGetSymbolAddress((void**)&pT, g_T);

    const int M = Bb * Ss;       // 4096
    const int N = Hh * DHd;      // 768
    const int Kd = Dd;           // 768

    cudaFuncSetAttribute(tgemm_k<true>,
                         cudaFuncAttributeMaxDynamicSharedMemorySize, GEMM_SMEM);
    cudaFuncSetAttribute(tgemm_k<false>,
                         cudaFuncAttributeMaxDynamicSharedMemorySize, GEMM_SMEM);
    cudaFuncSetAttribute(attn_k,
                         cudaFuncAttributeMaxDynamicSharedMemorySize, ATTN_SMEM);

    // Pre-round GEMM operands + rotary table
    round3_k<<<dim3(3072, 3), 256>>>(qin, kin, vin, pAq, pAk, pAv);
    round4_k<<<dim3(576, 4), 256>>>(WQ, WK, WV, WO, pWq, pWk, pWv, pWo);
    table_k<<<Ss * 32 / 256, 256>>>(pT);

    // Fused QKV projections (C stored head-major)
    tgemm_k<true><<<dim3(N / 128, M / 128, 3), 256, GEMM_SMEM>>>(
        pAq, pAk, pAv, pWq, pWk, pWv, bQ, bK, bV, pQ, pK, pV, M, N, Kd);

    // Attention (head-major tiles; rotary fused; scores+PV on tensor cores)
    attn_k<<<dim3(Ss / 64, Hh, Bb), 256, ATTN_SMEM>>>(pQ, pK, pV, pT, pZ);

    // Output projection (A gathered from head-major Z)
    tgemm_k<false><<<dim3(N / 128, M / 128, 1), 256, GEMM_SMEM>>>(
        pZ, pZ, pZ, pWo, pWo, pWo, bO, bO, bO, out, out, out, M, N, Kd);
}

// round 13
// speedup vs baseline: 1.2322x; 1.0350x over previous
#include <cuda_runtime.h>
#include <math.h>
#include <stdint.h>

// Problem constants
constexpr int Bb = 2;
constexpr int Ss = 2048;
constexpr int Dd = 768;
constexpr int Hh = 12;
constexpr int DHd = 64;
constexpr int WIN = 128;

// Scratch (device globals; no allocation allowed)
// Q/K/V/Z are HEAD-MAJOR: [b][h][s][d], plane stride Ss*64 = 131072 = 1<<17
__device__ __align__(16) float g_Q[Bb * Hh * Ss * DHd];
__device__ __align__(16) float g_K[Bb * Hh * Ss * DHd];
__device__ __align__(16) float g_V[Bb * Hh * Ss * DHd];
__device__ __align__(16) float g_Z[Bb * Hh * Ss * DHd];
// tf32-pre-rounded operands
__device__ __align__(16) float g_Aq[Bb * Ss * Dd];
__device__ __align__(16) float g_Ak[Bb * Ss * Dd];
__device__ __align__(16) float g_Av[Bb * Ss * Dd];
__device__ __align__(16) float g_Wq[Hh * Dd * DHd];
__device__ __align__(16) float g_Wk[Hh * Dd * DHd];
__device__ __align__(16) float g_Wv[Hh * Dd * DHd];
__device__ __align__(16) float g_Wo[Hh * DHd * Dd];
// rotary sin/cos table: [pos][freq] -> (sin, cos)
__device__ __align__(16) float2 g_T[Ss * 32];

__device__ __forceinline__ uint32_t f2tf32(float x) {
    uint32_t u;
    asm("cvt.rna.tf32.f32 %0, %1;" : "=r"(u) : "f"(x));
    return u;
}
__device__ __forceinline__ float round_tf32(float x) {
    return __uint_as_float(f2tf32(x));
}
__device__ __forceinline__ void cpa16(uint32_t dst, const void* src) {
    asm volatile("cp.async.cg.shared.global [%0], [%1], 16;"
                 :: "r"(dst), "l"(src) : "memory");
}
// zero-fill variant: src-size 0 -> writes 16 zero bytes (no gmem access of src)
__device__ __forceinline__ void cpa16p(uint32_t dst, const void* src, bool pred) {
    int sz = pred ? 16 : 0;
    asm volatile("cp.async.cg.shared.global [%0], [%1], 16, %2;"
                 :: "r"(dst), "l"(src), "r"(sz) : "memory");
}
#define CP_COMMIT() asm volatile("cp.async.commit_group;" ::: "memory")
#define CP_WAIT1()  asm volatile("cp.async.wait_group 1;" ::: "memory")
#define CP_WAIT0()  asm volatile("cp.async.wait_group 0;" ::: "memory")

#define MMA_TF32(acc, a, b)                                                   \
    asm volatile(                                                             \
        "mma.sync.aligned.m16n8k8.row.col.f32.tf32.tf32.f32 "                 \
        "{%0,%1,%2,%3}, {%4,%5,%6,%7}, {%8,%9}, {%0,%1,%2,%3};\n"             \
        : "+f"((acc)[0]), "+f"((acc)[1]), "+f"((acc)[2]), "+f"((acc)[3])      \
        : "r"((a)[0]), "r"((a)[1]), "r"((a)[2]), "r"((a)[3]),                 \
          "r"((b)[0]), "r"((b)[1]))

// ---------------------------------------------------------------------------
// Fused init: rounds 3 activations + 4 weights, builds rotary table.
// Flat grid: [0,9216) act, [9216,11520) weights, [11520,11776) table.
// ---------------------------------------------------------------------------
__global__ __launch_bounds__(256) void init_k(
    const float* __restrict__ a0, const float* __restrict__ a1,
    const float* __restrict__ a2,
    const float* __restrict__ w0, const float* __restrict__ w1,
    const float* __restrict__ w2, const float* __restrict__ w3,
    float* __restrict__ da0, float* __restrict__ da1, float* __restrict__ da2,
    float* __restrict__ dw0, float* __restrict__ dw1,
    float* __restrict__ dw2, float* __restrict__ dw3,
    float2* __restrict__ T)
{
    int bid = blockIdx.x;
    if (bid < 9216) {
        int tz = bid / 3072;                 // which activation tensor
        int idx = (bid % 3072) * 256 + threadIdx.x;
        const float* s = (tz == 0) ? a0 : (tz == 1) ? a1 : a2;
        float*       d = (tz == 0) ? da0 : (tz == 1) ? da1 : da2;
        float4 v = ((const float4*)s)[idx];
        v.x = round_tf32(v.x); v.y = round_tf32(v.y);
        v.z = round_tf32(v.z); v.w = round_tf32(v.w);
        ((float4*)d)[idx] = v;
    } else if (bid < 11520) {
        int r = bid - 9216;
        int tz = r / 576;
        int idx = (r % 576) * 256 + threadIdx.x;
        const float* s = (tz == 0) ? w0 : (tz == 1) ? w1 : (tz == 2) ? w2 : w3;
        float*       d = (tz == 0) ? dw0 : (tz == 1) ? dw1 : (tz == 2) ? dw2 : dw3;
        float4 v = ((const float4*)s)[idx];
        v.x = round_tf32(v.x); v.y = round_tf32(v.y);
        v.z = round_tf32(v.z); v.w = round_tf32(v.w);
        ((float4*)d)[idx] = v;
    } else {
        int tid = (bid - 11520) * 256 + threadIdx.x;   // 0..65535
        int s = tid >> 5;
        int i = tid & 31;
        float inv_freq = expf(-(float)(2 * i) * (1.0f / 64.0f) * 9.210340371976184f);
        float ang = (float)s * inv_freq;
        float sn, cs;
        sincosf(ang, &sn, &cs);
        T[tid] = make_float2(sn, cs);
    }
}

// ---------------------------------------------------------------------------
// tf32 mma GEMM, cp.async 3-stage, BM=128 BN=128 BK=32, 256 thr = 8 warps
// (2m x 4n, warp tile 64x32).  round_z: instance whose OUTPUT is tf32-rounded
// at the epilogue (used for V so attention can cp.async it raw). -1 = none.
// ---------------------------------------------------------------------------
constexpr int AW = 36;
constexpr int BWp = 136;
constexpr int SAW = 128 * AW;
constexpr int SBW = 32 * BWp;
constexpr int STW = SAW + SBW;
constexpr int NST = 3;
constexpr int GEMM_SMEM = NST * STW * 4;
constexpr int ITERS = 24;

template <bool HEADB>
__global__ __launch_bounds__(256, 2) void tgemm_k(
    const float* __restrict__ A0, const float* __restrict__ A1, const float* __restrict__ A2,
    const float* __restrict__ Bm0, const float* __restrict__ Bm1, const float* __restrict__ Bm2,
    const float* __restrict__ bias0, const float* __restrict__ bias1, const float* __restrict__ bias2,
    float* __restrict__ C0, float* __restrict__ C1, float* __restrict__ C2,
    int M, int N, int K, int round_z)
{
    extern __shared__ float smf[];
    const uint32_t smb = (uint32_t)__cvta_generic_to_shared(smf);

    const int z = blockIdx.z;
    const float* A    = (z == 0) ? A0    : (z == 1) ? A1    : A2;
    const float* Bm   = (z == 0) ? Bm0   : (z == 1) ? Bm1   : Bm2;
    const float* bias = (z == 0) ? bias0 : (z == 1) ? bias1 : bias2;
    float*       C    = (z == 0) ? C0    : (z == 1) ? C1    : C2;

    const int t    = threadIdx.x;
    const int m0   = blockIdx.y * 128;
    const int n0   = blockIdx.x * 128;
    const int warp = t >> 5;
    const int lane = t & 31;
    const int wm   = (warp >> 2) * 64;
    const int wn   = (warp & 3) * 32;
    const int group = lane >> 2;
    const int tig   = lane & 3;

    const int ar = t >> 3;
    const int ac = (t & 7) * 4;
    const int br = t >> 3;
    const int bc = (t & 7) * 4;

    auto issue_stage = [&](int s, int k0) {
        const uint32_t abase = smb + (uint32_t)(s * STW) * 4;
        const uint32_t bbase = abase + SAW * 4;
#pragma unroll
        for (int i = 0; i < 4; i++) {
            int r = ar + i * 32;
            const float* asrc;
            if (HEADB) {
                asrc = &A[(size_t)(m0 + r) * K + k0 + ac];
            } else {
                int m  = m0 + r;
                int b2 = m >> 11, s2 = m & 2047;
                int k  = k0 + ac;
                int h2 = k >> 6,  d2 = k & 63;
                asrc = &A[(((size_t)(b2 * Hh + h2)) << 17) + s2 * 64 + d2];
            }
            cpa16(abase + (uint32_t)(r * AW + ac) * 4, asrc);
        }
#pragma unroll
        for (int j = 0; j < 4; j++) {
            int col = bc + j * 32;
            const float* src;
            if (HEADB)
                src = Bm + (size_t)((n0 + col) >> 6) * K * 64
                         + (size_t)(k0 + br) * 64 + (col & 63);
            else
                src = Bm + (size_t)(k0 + br) * N + n0 + col;
            cpa16(bbase + (uint32_t)(br * BWp + col) * 4, src);
        }
        CP_COMMIT();
    };

    float acc[4][4][4];
#pragma unroll
    for (int mt = 0; mt < 4; mt++)
#pragma unroll
        for (int nt = 0; nt < 4; nt++)
#pragma unroll
            for (int j = 0; j < 4; j++) acc[mt][nt][j] = 0.0f;

    issue_stage(0, 0);
    issue_stage(1, 32);

    for (int it = 0; it < ITERS; it++) {
        CP_WAIT1();
        __syncthreads();
        if (it + 2 < ITERS) issue_stage((it + 2) % NST, (it + 2) * 32);
        else                CP_COMMIT();

        const float* As = smf + (it % NST) * STW;
        const float* Bs = As + SAW;

#pragma unroll
        for (int kk = 0; kk < 4; kk++) {
            const int k8 = kk * 8;
            uint32_t a[4][4], b[4][2];
#pragma unroll
            for (int mt = 0; mt < 4; mt++) {
                int r = wm + mt * 16 + group;
                a[mt][0] = __float_as_uint(As[r * AW + k8 + tig]);
                a[mt][1] = __float_as_uint(As[(r + 8) * AW + k8 + tig]);
                a[mt][2] = __float_as_uint(As[r * AW + k8 + tig + 4]);
                a[mt][3] = __float_as_uint(As[(r + 8) * AW + k8 + tig + 4]);
            }
#pragma unroll
            for (int nt = 0; nt < 4; nt++) {
                int cc = wn + nt * 8 + group;
                b[nt][0] = __float_as_uint(Bs[(k8 + tig) * BWp + cc]);
                b[nt][1] = __float_as_uint(Bs[(k8 + tig + 4) * BWp + cc]);
            }
#pragma unroll
            for (int mt = 0; mt < 4; mt++)
#pragma unroll
                for (int nt = 0; nt < 4; nt++)
                    MMA_TF32(acc[mt][nt], a[mt], b[nt]);
        }
    }

    const bool rz = (z == round_z);
#pragma unroll
    for (int mt = 0; mt < 4; mt++) {
#pragma unroll
        for (int nt = 0; nt < 4; nt++) {
            int col  = n0 + wn + nt * 8 + tig * 2;
            float bx = bias[col];
            float by = bias[col + 1];
            int r0 = m0 + wm + mt * 16 + group;
            float2 o0 = make_float2(acc[mt][nt][0] + bx, acc[mt][nt][1] + by);
            float2 o1 = make_float2(acc[mt][nt][2] + bx, acc[mt][nt][3] + by);
            if (rz) {
                o0.x = round_tf32(o0.x); o0.y = round_tf32(o0.y);
                o1.x = round_tf32(o1.x); o1.y = round_tf32(o1.y);
            }
            if (HEADB) {
                int b2 = r0 >> 11, s2 = r0 & 2047;
                int h2 = col >> 6, d2 = col & 63;
                float* dst = &C[(((size_t)(b2 * Hh + h2)) << 17) + s2 * 64 + d2];
                *(float2*)dst         = o0;
                *(float2*)(dst + 512) = o1;
            } else {
                *(float2*)&C[(size_t)r0 * N + col]       = o0;
                *(float2*)&C[(size_t)(r0 + 8) * N + col] = o1;
            }
        }
    }
}

// ---------------------------------------------------------------------------
// Tensor-core sliding-window attention; head-major I/O; V via double-buffered
// cp.async (V pre-rounded at GEMM epilogue).
// Smem (floats): Qs@0 p68 | Kd@4352 p200 | Sc@4608 p196 | V0@0 p72 | V1@17152
// ---------------------------------------------------------------------------
constexpr int QSP = 68;
constexpr int VPP = 72;
constexpr int KDP = 200;
constexpr int SCP = 196;
constexpr int OFF_KD = 4352;
constexpr int OFF_SC = 4608;
constexpr int OFF_V1 = 17152;
constexpr int ATTN_SMEM = (OFF_V1 + 64 * VPP) * 4;   // 87040 B

__global__ __launch_bounds__(256) void attn_k(
    const float* __restrict__ Q, const float* __restrict__ K,
    const float* __restrict__ V, const float2* __restrict__ T,
    float* __restrict__ Z)
{
    extern __shared__ float sm[];
    const uint32_t smb = (uint32_t)__cvta_generic_to_shared(sm);
    float* Qs = sm;
    float* Kd = sm + OFF_KD;
    float* Sc = sm + OFF_SC;

    const int t  = threadIdx.x;
    const int q0 = blockIdx.x * 64;
    const int h  = blockIdx.y;
    const int b  = blockIdx.z;

    const int warp  = t >> 5;
    const int lane  = t & 31;
    const int group = lane >> 2;
    const int tig   = lane & 3;

    const size_t plane = ((size_t)(b * Hh + h)) << 17;
    const float* Qh = Q + plane;
    const float* Kh = K + plane;
    const float* Vh = V + plane;
    float*       Zh = Z + plane;

    // V chunk issue helper: chunk c (keys q0-128+c*64 ..+63) -> buffer vb
    auto issue_V = [&](int c, int vb) {
        const uint32_t vbase = smb + (uint32_t)(vb ? OFF_V1 : 0) * 4;
#pragma unroll
        for (int i = 0; i < 4; i++) {
            int idx = t + i * 256;          // 0..1023
            int key = idx >> 4;             // 0..63
            int c4  = (idx & 15) * 4;       // 0..60
            int jg  = q0 - 128 + c * 64 + key;
            cpa16p(vbase + (uint32_t)(key * VPP + c4) * 4,
                   Vh + (size_t)jg * 64 + c4, jg >= 0);
        }
        CP_COMMIT();
    };

    // ---- Q loader: contiguous rows, rotated + tf32-rounded, q-major ----
#pragma unroll
    for (int i = 0; i < 2; i++) {
        int idx = t + i * 256;
        int row = idx >> 3;
        int c4  = (idx & 7) * 4;
        int qg  = q0 + row;
        const float* src = Qh + (size_t)qg * 64;
        float4 x = *(const float4*)&src[c4];
        float4 y = *(const float4*)&src[c4 + 32];
        float xa[4] = {x.x, x.y, x.z, x.w};
        float ya[4] = {y.x, y.y, y.z, y.w};
        float4 lo, hi;
        float* lop = &lo.x; float* hip = &hi.x;
#pragma unroll
        for (int j = 0; j < 4; j++) {
            float2 sc = T[qg * 32 + c4 + j];
            lop[j] = round_tf32(xa[j] * sc.y - ya[j] * sc.x);
            hip[j] = round_tf32(ya[j] * sc.y + xa[j] * sc.x);
        }
        *(float4*)&Qs[row * QSP + c4]      = lo;
        *(float4*)&Qs[row * QSP + c4 + 32] = hi;
    }
    // ---- K loader: 192 contiguous keys, rotated + rounded, d-major ----
#pragma unroll
    for (int i = 0; i < 6; i++) {
        int idx = t + i * 256;
        int key = idx >> 3;
        int c4  = (idx & 7) * 4;
        int jg  = q0 - 128 + key;
        float lov[4] = {0.f, 0.f, 0.f, 0.f};
        float hiv[4] = {0.f, 0.f, 0.f, 0.f};
        if (jg >= 0) {
            const float* src = Kh + (size_t)jg * 64;
            float4 x = *(const float4*)&src[c4];
            float4 y = *(const float4*)&src[c4 + 32];
            float xa[4] = {x.x, x.y, x.z, x.w};
            float ya[4] = {y.x, y.y, y.z, y.w};
#pragma unroll
            for (int j = 0; j < 4; j++) {
                float2 sc = T[jg * 32 + c4 + j];
                lov[j] = round_tf32(xa[j] * sc.y - ya[j] * sc.x);
                hiv[j] = round_tf32(ya[j] * sc.y + xa[j] * sc.x);
            }
        }
#pragma unroll
        for (int j = 0; j < 4; j++) {
            Kd[(c4 + j) * KDP + key]      = lov[j];
            Kd[(c4 + j + 32) * KDP + key] = hiv[j];
        }
    }
    __syncthreads();

    // ---- scores mma: warp tile 32q x 48key (2m x 4n warps), K=64 ----
    {
        const int wm = (warp >> 2) * 32;
        const int wn = (warp & 3) * 48;
        float acc[2][6][4];
#pragma unroll
        for (int mt = 0; mt < 2; mt++)
#pragma unroll
            for (int nt = 0; nt < 6; nt++)
#pragma unroll
                for (int j = 0; j < 4; j++) acc[mt][nt][j] = 0.0f;

#pragma unroll
        for (int kk = 0; kk < 8; kk++) {
            const int k8 = kk * 8;
            uint32_t a[2][4], bf[6][2];
#pragma unroll
            for (int mt = 0; mt < 2; mt++) {
                int r = wm + mt * 16 + group;
                a[mt][0] = __float_as_uint(Qs[r * QSP + k8 + tig]);
                a[mt][1] = __float_as_uint(Qs[(r + 8) * QSP + k8 + tig]);
                a[mt][2] = __float_as_uint(Qs[r * QSP + k8 + tig + 4]);
                a[mt][3] = __float_as_uint(Qs[(r + 8) * QSP + k8 + tig + 4]);
            }
#pragma unroll
            for (int nt = 0; nt < 6; nt++) {
                int col = wn + nt * 8 + group;
                bf[nt][0] = __float_as_uint(Kd[(k8 + tig) * KDP + col]);
                bf[nt][1] = __float_as_uint(Kd[(k8 + tig + 4) * KDP + col]);
            }
#pragma unroll
            for (int mt = 0; mt < 2; mt++)
#pragma unroll
                for (int nt = 0; nt < 6; nt++)
                    MMA_TF32(acc[mt][nt], a[mt], bf[nt]);
        }
        __syncthreads();   // Qs + Kd reads done; V0 may overwrite Qs, Sc over Kd tail

        // start streaming V chunks 0 and 1 (overlaps epilogue + softmax)
        issue_V(0, 0);
        issue_V(1, 1);

        // masked/scaled epilogue -> Sc
#pragma unroll
        for (int mt = 0; mt < 2; mt++) {
#pragma unroll
            for (int nt = 0; nt < 6; nt++) {
                int col = wn + nt * 8 + tig * 2;
                int jgl = q0 - 128 + col;
#pragma unroll
                for (int hl = 0; hl < 2; hl++) {
                    int r  = wm + mt * 16 + group + hl * 8;
                    int qg = q0 + r;
                    bool ok0 = (jgl >= 0) && (jgl <= qg) && (jgl > qg - WIN);
                    bool ok1 = (jgl + 1 >= 0) && (jgl + 1 <= qg) && (jgl + 1 > qg - WIN);
                    float2 o;
                    o.x = ok0 ? acc[mt][nt][hl * 2 + 0] * 0.125f : -1e30f;
                    o.y = ok1 ? acc[mt][nt][hl * 2 + 1] * 0.125f : -1e30f;
                    *(float2*)&Sc[r * SCP + col] = o;
                }
            }
        }
    }
    __syncthreads();

    // ---- softmax (V0/V1 streaming in behind) ----
    {
        int r = t >> 2;
        int p = t & 3;
        float mx = -1e30f;
        for (int jj = p * 48; jj < p * 48 + 48; jj++)
            mx = fmaxf(mx, Sc[r * SCP + jj]);
        mx = fmaxf(mx, __shfl_xor_sync(0xFFFFFFFFu, mx, 1));
        mx = fmaxf(mx, __shfl_xor_sync(0xFFFFFFFFu, mx, 2));
        float sum = 0.0f;
        for (int jj = p * 48; jj < p * 48 + 48; jj++) {
            float e = __expf(Sc[r * SCP + jj] - mx);
            Sc[r * SCP + jj] = e;
            sum += e;
        }
        sum += __shfl_xor_sync(0xFFFFFFFFu, sum, 1);
        sum += __shfl_xor_sync(0xFFFFFFFFu, sum, 2);
        float inv = 1.0f / sum;
        for (int jj = p * 48; jj < p * 48 + 48; jj++)
            Sc[r * SCP + jj] = round_tf32(Sc[r * SCP + jj] * inv);
    }
    __syncthreads();   // softmax visible to all before PV

    // ---- PV mma: warp tile 32q x 16d, K=192 in 3 double-buffered chunks ----
    {
        const int wm = (warp >> 2) * 32;
        const int wn = (warp & 3) * 16;
        float acc[2][2][4];
#pragma unroll
        for (int mt = 0; mt < 2; mt++)
#pragma unroll
            for (int nt = 0; nt < 2; nt++)
#pragma unroll
                for (int j = 0; j < 4; j++) acc[mt][nt][j] = 0.0f;

        for (int c = 0; c < 3; c++) {
            if (c == 0)      { CP_WAIT1(); }          // V0 landed (V1 pending)
            else if (c == 1) { CP_WAIT1(); }          // V1 landed (V2 pending)
            else             { CP_WAIT0(); }          // V2 landed
            __syncthreads();
            const float* Vv = sm + ((c & 1) ? OFF_V1 : 0);

#pragma unroll
            for (int kk = 0; kk < 8; kk++) {
                const int k8 = kk * 8;
                uint32_t a[2][4], bf[2][2];
#pragma unroll
                for (int mt = 0; mt < 2; mt++) {
                    int r = wm + mt * 16 + group;
                    int scol = c * 64 + k8 + tig;
                    a[mt][0] = __float_as_uint(Sc[r * SCP + scol]);
                    a[mt][1] = __float_as_uint(Sc[(r + 8) * SCP + scol]);
                    a[mt][2] = __float_as_uint(Sc[r * SCP + scol + 4]);
                    a[mt][3] = __float_as_uint(Sc[(r + 8) * SCP + scol + 4]);
                }
#pragma unroll
                for (int nt = 0; nt < 2; nt++) {
                    int dcol = wn + nt * 8 + group;
                    bf[nt][0] = __float_as_uint(Vv[(k8 + tig) * VPP + dcol]);
                    bf[nt][1] = __float_as_uint(Vv[(k8 + tig + 4) * VPP + dcol]);
                }
#pragma unroll
                for (int mt = 0; mt < 2; mt++)
#pragma unroll
                    for (int nt = 0; nt < 2; nt++)
                        MMA_TF32(acc[mt][nt], a[mt], bf[nt]);
            }

            if (c == 0) {
                __syncthreads();       // all warps done reading V0
                issue_V(2, 0);         // stream chunk 2 into buffer 0
            }
        }

        // epilogue -> Z (head-major, tf32-rounded)
#pragma unroll
        for (int mt = 0; mt < 2; mt++) {
#pragma unroll
            for (int nt = 0; nt < 2; nt++) {
                int col = wn + nt * 8 + tig * 2;
#pragma unroll
                for (int hl = 0; hl < 2; hl++) {
                    int r = wm + mt * 16 + group + hl * 8;
                    float2 o;
                    o.x = round_tf32(acc[mt][nt][hl * 2 + 0]);
                    o.y = round_tf32(acc[mt][nt][hl * 2 + 1]);
                    *(float2*)&Zh[(size_t)(q0 + r) * 64 + col] = o;
                }
            }
        }
    }
}

// ---------------------------------------------------------------------------
extern "C" void kernel_launch(void* const* d_in, const int* in_sizes, int n_in,
                              void* d_out, int out_size)
{
    const float* qin = (const float*)d_in[0];
    const float* kin = (const float*)d_in[1];
    const float* vin = (const float*)d_in[2];
    const float* WQ  = (const float*)d_in[3];
    const float* WK  = (const float*)d_in[4];
    const float* WV  = (const float*)d_in[5];
    const float* WO  = (const float*)d_in[6];
    const float* bQ  = (const float*)d_in[7];
    const float* bK  = (const float*)d_in[8];
    const float* bV  = (const float*)d_in[9];
    const float* bO  = (const float*)d_in[10];
    float* out = (float*)d_out;

    float *pQ, *pK, *pV, *pZ;
    float *pAq, *pAk, *pAv, *pWq, *pWk, *pWv, *pWo;
    float2* pT;
    cudaGetSymbolAddress((void**)&pQ, g_Q);
    cudaGetSymbolAddress((void**)&pK, g_K);
    cudaGetSymbolAddress((void**)&pV, g_V);
    cudaGetSymbolAddress((void**)&pZ, g_Z);
    cudaGetSymbolAddress((void**)&pAq, g_Aq);
    cudaGetSymbolAddress((void**)&pAk, g_Ak);
    cudaGetSymbolAddress((void**)&pAv, g_Av);
    cudaGetSymbolAddress((void**)&pWq, g_Wq);
    cudaGetSymbolAddress((void**)&pWk, g_Wk);
    cudaGetSymbolAddress((void**)&pWv, g_Wv);
    cudaGetSymbolAddress((void**)&pWo, g_Wo);
    cudaGetSymbolAddress((void**)&pT, g_T);

    const int M = Bb * Ss;       // 4096
    const int N = Hh * DHd;      // 768
    const int Kd = Dd;           // 768

    cudaFuncSetAttribute(tgemm_k<true>,
                         cudaFuncAttributeMaxDynamicSharedMemorySize, GEMM_SMEM);
    cudaFuncSetAttribute(tgemm_k<false>,
                         cudaFuncAttributeMaxDynamicSharedMemorySize, GEMM_SMEM);
    cudaFuncSetAttribute(attn_k,
                         cudaFuncAttributeMaxDynamicSharedMemorySize, ATTN_SMEM);

    // Fused init: pre-round operands + rotary table (one launch)
    init_k<<<11776, 256>>>(qin, kin, vin, WQ, WK, WV, WO,
                           pAq, pAk, pAv, pWq, pWk, pWv, pWo, pT);

    // Fused QKV projections (C head-major; V output pre-rounded: round_z=2)
    tgemm_k<true><<<dim3(N / 128, M / 128, 3), 256, GEMM_SMEM>>>(
        pAq, pAk, pAv, pWq, pWk, pWv, bQ, bK, bV, pQ, pK, pV, M, N, Kd, 2);

    // Attention (head-major; rotary fused; V double-buffered cp.async)
    attn_k<<<dim3(Ss / 64, Hh, Bb), 256, ATTN_SMEM>>>(pQ, pK, pV, pT, pZ);

    // Output projection
    tgemm_k<false><<<dim3(N / 128, M / 128, 1), 256, GEMM_SMEM>>>(
        pZ, pZ, pZ, pWo, pWo, pWo, bO, bO, bO, out, out, out, M, N, Kd, -1);
}

// round 14
// speedup vs baseline: 1.2419x; 1.0079x over previous
#include <cuda_runtime.h>
#include <math.h>
#include <stdint.h>

// Problem constants
constexpr int Bb = 2;
constexpr int Ss = 2048;
constexpr int Dd = 768;
constexpr int Hh = 12;
constexpr int DHd = 64;
constexpr int WIN = 128;

// Scratch (device globals; no allocation allowed)
// Q/K/V/Z are HEAD-MAJOR: [b][h][s][d], plane stride Ss*64 = 131072 = 1<<17
__device__ __align__(16) float g_Q[Bb * Hh * Ss * DHd];
__device__ __align__(16) float g_K[Bb * Hh * Ss * DHd];
__device__ __align__(16) float g_V[Bb * Hh * Ss * DHd];
__device__ __align__(16) float g_Z[Bb * Hh * Ss * DHd];
// tf32-pre-rounded operands
__device__ __align__(16) float g_Aq[Bb * Ss * Dd];
__device__ __align__(16) float g_Ak[Bb * Ss * Dd];
__device__ __align__(16) float g_Av[Bb * Ss * Dd];
__device__ __align__(16) float g_Wq[Hh * Dd * DHd];
__device__ __align__(16) float g_Wk[Hh * Dd * DHd];
__device__ __align__(16) float g_Wv[Hh * Dd * DHd];
__device__ __align__(16) float g_Wo[Hh * DHd * Dd];
// rotary sin/cos table: [pos][freq] -> (sin, cos)
__device__ __align__(16) float2 g_T[Ss * 32];

__device__ __forceinline__ uint32_t f2tf32(float x) {
    uint32_t u;
    asm("cvt.rna.tf32.f32 %0, %1;" : "=r"(u) : "f"(x));
    return u;
}
__device__ __forceinline__ float round_tf32(float x) {
    return __uint_as_float(f2tf32(x));
}
__device__ __forceinline__ void cpa16(uint32_t dst, const void* src) {
    asm volatile("cp.async.cg.shared.global [%0], [%1], 16;"
                 :: "r"(dst), "l"(src) : "memory");
}
// zero-fill variant: src-size 0 -> writes 16 zero bytes
__device__ __forceinline__ void cpa16p(uint32_t dst, const void* src, bool pred) {
    int sz = pred ? 16 : 0;
    asm volatile("cp.async.cg.shared.global [%0], [%1], 16, %2;"
                 :: "r"(dst), "l"(src), "r"(sz) : "memory");
}
#define CP_COMMIT() asm volatile("cp.async.commit_group;" ::: "memory")
#define CP_WAIT1()  asm volatile("cp.async.wait_group 1;" ::: "memory")
#define CP_WAIT0()  asm volatile("cp.async.wait_group 0;" ::: "memory")

#define MMA_TF32(acc, a, b)                                                   \
    asm volatile(                                                             \
        "mma.sync.aligned.m16n8k8.row.col.f32.tf32.tf32.f32 "                 \
        "{%0,%1,%2,%3}, {%4,%5,%6,%7}, {%8,%9}, {%0,%1,%2,%3};\n"             \
        : "+f"((acc)[0]), "+f"((acc)[1]), "+f"((acc)[2]), "+f"((acc)[3])      \
        : "r"((a)[0]), "r"((a)[1]), "r"((a)[2]), "r"((a)[3]),                 \
          "r"((b)[0]), "r"((b)[1]))

// ---------------------------------------------------------------------------
// Fused init: rounds 3 activations + 4 weights, builds rotary table.
// ---------------------------------------------------------------------------
__global__ __launch_bounds__(256) void init_k(
    const float* __restrict__ a0, const float* __restrict__ a1,
    const float* __restrict__ a2,
    const float* __restrict__ w0, const float* __restrict__ w1,
    const float* __restrict__ w2, const float* __restrict__ w3,
    float* __restrict__ da0, float* __restrict__ da1, float* __restrict__ da2,
    float* __restrict__ dw0, float* __restrict__ dw1,
    float* __restrict__ dw2, float* __restrict__ dw3,
    float2* __restrict__ T)
{
    int bid = blockIdx.x;
    if (bid < 9216) {
        int tz = bid / 3072;
        int idx = (bid % 3072) * 256 + threadIdx.x;
        const float* s = (tz == 0) ? a0 : (tz == 1) ? a1 : a2;
        float*       d = (tz == 0) ? da0 : (tz == 1) ? da1 : da2;
        float4 v = ((const float4*)s)[idx];
        v.x = round_tf32(v.x); v.y = round_tf32(v.y);
        v.z = round_tf32(v.z); v.w = round_tf32(v.w);
        ((float4*)d)[idx] = v;
    } else if (bid < 11520) {
        int r = bid - 9216;
        int tz = r / 576;
        int idx = (r % 576) * 256 + threadIdx.x;
        const float* s = (tz == 0) ? w0 : (tz == 1) ? w1 : (tz == 2) ? w2 : w3;
        float*       d = (tz == 0) ? dw0 : (tz == 1) ? dw1 : (tz == 2) ? dw2 : dw3;
        float4 v = ((const float4*)s)[idx];
        v.x = round_tf32(v.x); v.y = round_tf32(v.y);
        v.z = round_tf32(v.z); v.w = round_tf32(v.w);
        ((float4*)d)[idx] = v;
    } else {
        int tid = (bid - 11520) * 256 + threadIdx.x;
        int s = tid >> 5;
        int i = tid & 31;
        float inv_freq = expf(-(float)(2 * i) * (1.0f / 64.0f) * 9.210340371976184f);
        float ang = (float)s * inv_freq;
        float sn, cs;
        sincosf(ang, &sn, &cs);
        T[tid] = make_float2(sn, cs);
    }
}

// ---------------------------------------------------------------------------
// QKV GEMM (unchanged round-13 config): BM=128 BN=128 BK=32, 8 warps 2m x 4n,
// 3-stage cp.async, C head-major, round_z output rounding.
// ---------------------------------------------------------------------------
constexpr int AW = 36;
constexpr int BWp = 136;
constexpr int SAW = 128 * AW;
constexpr int SBW = 32 * BWp;
constexpr int STW = SAW + SBW;
constexpr int NST = 3;
constexpr int GEMM_SMEM = NST * STW * 4;
constexpr int ITERS = 24;

__global__ __launch_bounds__(256, 2) void tgemm_k(
    const float* __restrict__ A0, const float* __restrict__ A1, const float* __restrict__ A2,
    const float* __restrict__ Bm0, const float* __restrict__ Bm1, const float* __restrict__ Bm2,
    const float* __restrict__ bias0, const float* __restrict__ bias1, const float* __restrict__ bias2,
    float* __restrict__ C0, float* __restrict__ C1, float* __restrict__ C2,
    int M, int N, int K, int round_z)
{
    extern __shared__ float smf[];
    const uint32_t smb = (uint32_t)__cvta_generic_to_shared(smf);

    const int z = blockIdx.z;
    const float* A    = (z == 0) ? A0    : (z == 1) ? A1    : A2;
    const float* Bm   = (z == 0) ? Bm0   : (z == 1) ? Bm1   : Bm2;
    const float* bias = (z == 0) ? bias0 : (z == 1) ? bias1 : bias2;
    float*       C    = (z == 0) ? C0    : (z == 1) ? C1    : C2;

    const int t    = threadIdx.x;
    const int m0   = blockIdx.y * 128;
    const int n0   = blockIdx.x * 128;
    const int warp = t >> 5;
    const int lane = t & 31;
    const int wm   = (warp >> 2) * 64;
    const int wn   = (warp & 3) * 32;
    const int group = lane >> 2;
    const int tig   = lane & 3;

    const int ar = t >> 3;
    const int ac = (t & 7) * 4;
    const int br = t >> 3;
    const int bc = (t & 7) * 4;

    auto issue_stage = [&](int s, int k0) {
        const uint32_t abase = smb + (uint32_t)(s * STW) * 4;
        const uint32_t bbase = abase + SAW * 4;
#pragma unroll
        for (int i = 0; i < 4; i++) {
            int r = ar + i * 32;
            cpa16(abase + (uint32_t)(r * AW + ac) * 4,
                  &A[(size_t)(m0 + r) * K + k0 + ac]);
        }
#pragma unroll
        for (int j = 0; j < 4; j++) {
            int col = bc + j * 32;
            const float* src = Bm + (size_t)((n0 + col) >> 6) * K * 64
                                  + (size_t)(k0 + br) * 64 + (col & 63);
            cpa16(bbase + (uint32_t)(br * BWp + col) * 4, src);
        }
        CP_COMMIT();
    };

    float acc[4][4][4];
#pragma unroll
    for (int mt = 0; mt < 4; mt++)
#pragma unroll
        for (int nt = 0; nt < 4; nt++)
#pragma unroll
            for (int j = 0; j < 4; j++) acc[mt][nt][j] = 0.0f;

    issue_stage(0, 0);
    issue_stage(1, 32);

    for (int it = 0; it < ITERS; it++) {
        CP_WAIT1();
        __syncthreads();
        if (it + 2 < ITERS) issue_stage((it + 2) % NST, (it + 2) * 32);
        else                CP_COMMIT();

        const float* As = smf + (it % NST) * STW;
        const float* Bs = As + SAW;

#pragma unroll
        for (int kk = 0; kk < 4; kk++) {
            const int k8 = kk * 8;
            uint32_t a[4][4], b[4][2];
#pragma unroll
            for (int mt = 0; mt < 4; mt++) {
                int r = wm + mt * 16 + group;
                a[mt][0] = __float_as_uint(As[r * AW + k8 + tig]);
                a[mt][1] = __float_as_uint(As[(r + 8) * AW + k8 + tig]);
                a[mt][2] = __float_as_uint(As[r * AW + k8 + tig + 4]);
                a[mt][3] = __float_as_uint(As[(r + 8) * AW + k8 + tig + 4]);
            }
#pragma unroll
            for (int nt = 0; nt < 4; nt++) {
                int cc = wn + nt * 8 + group;
                b[nt][0] = __float_as_uint(Bs[(k8 + tig) * BWp + cc]);
                b[nt][1] = __float_as_uint(Bs[(k8 + tig + 4) * BWp + cc]);
            }
#pragma unroll
            for (int mt = 0; mt < 4; mt++)
#pragma unroll
                for (int nt = 0; nt < 4; nt++)
                    MMA_TF32(acc[mt][nt], a[mt], b[nt]);
        }
    }

    const bool rz = (z == round_z);
#pragma unroll
    for (int mt = 0; mt < 4; mt++) {
#pragma unroll
        for (int nt = 0; nt < 4; nt++) {
            int col  = n0 + wn + nt * 8 + tig * 2;
            float bx = bias[col];
            float by = bias[col + 1];
            int r0 = m0 + wm + mt * 16 + group;
            float2 o0 = make_float2(acc[mt][nt][0] + bx, acc[mt][nt][1] + by);
            float2 o1 = make_float2(acc[mt][nt][2] + bx, acc[mt][nt][3] + by);
            if (rz) {
                o0.x = round_tf32(o0.x); o0.y = round_tf32(o0.y);
                o1.x = round_tf32(o1.x); o1.y = round_tf32(o1.y);
            }
            int b2 = r0 >> 11, s2 = r0 & 2047;
            int h2 = col >> 6, d2 = col & 63;
            float* dst = &C[(((size_t)(b2 * Hh + h2)) << 17) + s2 * 64 + d2];
            *(float2*)dst         = o0;
            *(float2*)(dst + 512) = o1;
        }
    }
}

// ---------------------------------------------------------------------------
// WO GEMM: BM=128, BN=64, BK=32, 8 warps 4m x 2n (warp tile 32x32),
// 2-stage cp.async, 3 CTAs/SM target. A gathered from head-major Z,
// B row-major (Wo pre-rounded), C row-major + bias.
// Grid: (N/64=12, M/128=32) = 384 blocks -> one wave at 3 CTA/SM.
// ---------------------------------------------------------------------------
constexpr int BW64 = 72;                  // B pitch (72 % 32 = 8 -> conflict-free)
constexpr int SB64 = 32 * BW64;           // 2304
constexpr int STW64 = SAW + SB64;         // 6912
constexpr int GEMM64_SMEM = 2 * STW64 * 4;   // 55296 B

__global__ __launch_bounds__(256, 3) void tgemm64_k(
    const float* __restrict__ A, const float* __restrict__ Bm,
    const float* __restrict__ bias, float* __restrict__ C,
    int M, int N, int K)
{
    extern __shared__ float smf[];
    const uint32_t smb = (uint32_t)__cvta_generic_to_shared(smf);

    const int t    = threadIdx.x;
    const int m0   = blockIdx.y * 128;
    const int n0   = blockIdx.x * 64;
    const int warp = t >> 5;
    const int lane = t & 31;
    const int wm   = (warp >> 1) * 32;   // 4 warps in m
    const int wn   = (warp & 1) * 32;    // 2 warps in n
    const int group = lane >> 2;
    const int tig   = lane & 3;

    const int ar = t >> 3;           // A rows ar + i*32
    const int ac = (t & 7) * 4;

    auto issue_stage = [&](int s, int k0) {
        const uint32_t abase = smb + (uint32_t)(s * STW64) * 4;
        const uint32_t bbase = abase + SAW * 4;
#pragma unroll
        for (int i = 0; i < 4; i++) {
            int r = ar + i * 32;
            // A = head-major Z: m=(b,s), k=(h,d); chunk stays in one head row
            int m  = m0 + r;
            int b2 = m >> 11, s2 = m & 2047;
            int k  = k0 + ac;
            int h2 = k >> 6,  d2 = k & 63;
            cpa16(abase + (uint32_t)(r * AW + ac) * 4,
                  &A[(((size_t)(b2 * Hh + h2)) << 17) + s2 * 64 + d2]);
        }
        // B tile 32 x 64 = 512 float4 chunks, 2 per thread
#pragma unroll
        for (int i = 0; i < 2; i++) {
            int idx = t + i * 256;          // 0..511
            int kr  = idx >> 4;             // 0..31
            int col = (idx & 15) * 4;       // 0..60
            cpa16(bbase + (uint32_t)(kr * BW64 + col) * 4,
                  Bm + (size_t)(k0 + kr) * N + n0 + col);
        }
        CP_COMMIT();
    };

    float acc[2][4][4];
#pragma unroll
    for (int mt = 0; mt < 2; mt++)
#pragma unroll
        for (int nt = 0; nt < 4; nt++)
#pragma unroll
            for (int j = 0; j < 4; j++) acc[mt][nt][j] = 0.0f;

    issue_stage(0, 0);

    for (int it = 0; it < ITERS; it++) {
        CP_WAIT0();
        __syncthreads();
        if (it + 1 < ITERS) issue_stage((it + 1) & 1, (it + 1) * 32);

        const float* As = smf + (it & 1) * STW64;
        const float* Bs = As + SAW;

#pragma unroll
        for (int kk = 0; kk < 4; kk++) {
            const int k8 = kk * 8;
            uint32_t a[2][4], b[4][2];
#pragma unroll
            for (int mt = 0; mt < 2; mt++) {
                int r = wm + mt * 16 + group;
                a[mt][0] = __float_as_uint(As[r * AW + k8 + tig]);
                a[mt][1] = __float_as_uint(As[(r + 8) * AW + k8 + tig]);
                a[mt][2] = __float_as_uint(As[r * AW + k8 + tig + 4]);
                a[mt][3] = __float_as_uint(As[(r + 8) * AW + k8 + tig + 4]);
            }
#pragma unroll
            for (int nt = 0; nt < 4; nt++) {
                int cc = wn + nt * 8 + group;
                b[nt][0] = __float_as_uint(Bs[(k8 + tig) * BW64 + cc]);
                b[nt][1] = __float_as_uint(Bs[(k8 + tig + 4) * BW64 + cc]);
            }
#pragma unroll
            for (int mt = 0; mt < 2; mt++)
#pragma unroll
                for (int nt = 0; nt < 4; nt++)
                    MMA_TF32(acc[mt][nt], a[mt], b[nt]);
        }
        __syncthreads();   // compute done before next iter's issue overwrites
    }

#pragma unroll
    for (int mt = 0; mt < 2; mt++) {
#pragma unroll
        for (int nt = 0; nt < 4; nt++) {
            int col  = n0 + wn + nt * 8 + tig * 2;
            float bx = bias[col];
            float by = bias[col + 1];
            int r0 = m0 + wm + mt * 16 + group;
            float2 o0 = make_float2(acc[mt][nt][0] + bx, acc[mt][nt][1] + by);
            float2 o1 = make_float2(acc[mt][nt][2] + bx, acc[mt][nt][3] + by);
            *(float2*)&C[(size_t)r0 * N + col]       = o0;
            *(float2*)&C[(size_t)(r0 + 8) * N + col] = o1;
        }
    }
}

// ---------------------------------------------------------------------------
// Tensor-core sliding-window attention (unchanged round 13).
// ---------------------------------------------------------------------------
constexpr int QSP = 68;
constexpr int VPP = 72;
constexpr int KDP = 200;
constexpr int SCP = 196;
constexpr int OFF_KD = 4352;
constexpr int OFF_SC = 4608;
constexpr int OFF_V1 = 17152;
constexpr int ATTN_SMEM = (OFF_V1 + 64 * VPP) * 4;

__global__ __launch_bounds__(256) void attn_k(
    const float* __restrict__ Q, const float* __restrict__ K,
    const float* __restrict__ V, const float2* __restrict__ T,
    float* __restrict__ Z)
{
    extern __shared__ float sm[];
    const uint32_t smb = (uint32_t)__cvta_generic_to_shared(sm);
    float* Qs = sm;
    float* Kd = sm + OFF_KD;
    float* Sc = sm + OFF_SC;

    const int t  = threadIdx.x;
    const int q0 = blockIdx.x * 64;
    const int h  = blockIdx.y;
    const int b  = blockIdx.z;

    const int warp  = t >> 5;
    const int lane  = t & 31;
    const int group = lane >> 2;
    const int tig   = lane & 3;

    const size_t plane = ((size_t)(b * Hh + h)) << 17;
    const float* Qh = Q + plane;
    const float* Kh = K + plane;
    const float* Vh = V + plane;
    float*       Zh = Z + plane;

    auto issue_V = [&](int c, int vb) {
        const uint32_t vbase = smb + (uint32_t)(vb ? OFF_V1 : 0) * 4;
#pragma unroll
        for (int i = 0; i < 4; i++) {
            int idx = t + i * 256;
            int key = idx >> 4;
            int c4  = (idx & 15) * 4;
            int jg  = q0 - 128 + c * 64 + key;
            cpa16p(vbase + (uint32_t)(key * VPP + c4) * 4,
                   Vh + (size_t)jg * 64 + c4, jg >= 0);
        }
        CP_COMMIT();
    };

#pragma unroll
    for (int i = 0; i < 2; i++) {
        int idx = t + i * 256;
        int row = idx >> 3;
        int c4  = (idx & 7) * 4;
        int qg  = q0 + row;
        const float* src = Qh + (size_t)qg * 64;
        float4 x = *(const float4*)&src[c4];
        float4 y = *(const float4*)&src[c4 + 32];
        float xa[4] = {x.x, x.y, x.z, x.w};
        float ya[4] = {y.x, y.y, y.z, y.w};
        float4 lo, hi;
        float* lop = &lo.x; float* hip = &hi.x;
#pragma unroll
        for (int j = 0; j < 4; j++) {
            float2 sc = T[qg * 32 + c4 + j];
            lop[j] = round_tf32(xa[j] * sc.y - ya[j] * sc.x);
            hip[j] = round_tf32(ya[j] * sc.y + xa[j] * sc.x);
        }
        *(float4*)&Qs[row * QSP + c4]      = lo;
        *(float4*)&Qs[row * QSP + c4 + 32] = hi;
    }
#pragma unroll
    for (int i = 0; i < 6; i++) {
        int idx = t + i * 256;
        int key = idx >> 3;
        int c4  = (idx & 7) * 4;
        int jg  = q0 - 128 + key;
        float lov[4] = {0.f, 0.f, 0.f, 0.f};
        float hiv[4] = {0.f, 0.f, 0.f, 0.f};
        if (jg >= 0) {
            const float* src = Kh + (size_t)jg * 64;
            float4 x = *(const float4*)&src[c4];
            float4 y = *(const float4*)&src[c4 + 32];
            float xa[4] = {x.x, x.y, x.z, x.w};
            float ya[4] = {y.x, y.y, y.z, y.w};
#pragma unroll
            for (int j = 0; j < 4; j++) {
                float2 sc = T[jg * 32 + c4 + j];
                lov[j] = round_tf32(xa[j] * sc.y - ya[j] * sc.x);
                hiv[j] = round_tf32(ya[j] * sc.y + xa[j] * sc.x);
            }
        }
#pragma unroll
        for (int j = 0; j < 4; j++) {
            Kd[(c4 + j) * KDP + key]      = lov[j];
            Kd[(c4 + j + 32) * KDP + key] = hiv[j];
        }
    }
    __syncthreads();

    {
        const int wm = (warp >> 2) * 32;
        const int wn = (warp & 3) * 48;
        float acc[2][6][4];
#pragma unroll
        for (int mt = 0; mt < 2; mt++)
#pragma unroll
            for (int nt = 0; nt < 6; nt++)
#pragma unroll
                for (int j = 0; j < 4; j++) acc[mt][nt][j] = 0.0f;

#pragma unroll
        for (int kk = 0; kk < 8; kk++) {
            const int k8 = kk * 8;
            uint32_t a[2][4], bf[6][2];
#pragma unroll
            for (int mt = 0; mt < 2; mt++) {
                int r = wm + mt * 16 + group;
                a[mt][0] = __float_as_uint(Qs[r * QSP + k8 + tig]);
                a[mt][1] = __float_as_uint(Qs[(r + 8) * QSP + k8 + tig]);
                a[mt][2] = __float_as_uint(Qs[r * QSP + k8 + tig + 4]);
                a[mt][3] = __float_as_uint(Qs[(r + 8) * QSP + k8 + tig + 4]);
            }
#pragma unroll
            for (int nt = 0; nt < 6; nt++) {
                int col = wn + nt * 8 + group;
                bf[nt][0] = __float_as_uint(Kd[(k8 + tig) * KDP + col]);
                bf[nt][1] = __float_as_uint(Kd[(k8 + tig + 4) * KDP + col]);
            }
#pragma unroll
            for (int mt = 0; mt < 2; mt++)
#pragma unroll
                for (int nt = 0; nt < 6; nt++)
                    MMA_TF32(acc[mt][nt], a[mt], bf[nt]);
        }
        __syncthreads();

        issue_V(0, 0);
        issue_V(1, 1);

#pragma unroll
        for (int mt = 0; mt < 2; mt++) {
#pragma unroll
            for (int nt = 0; nt < 6; nt++) {
                int col = wn + nt * 8 + tig * 2;
                int jgl = q0 - 128 + col;
#pragma unroll
                for (int hl = 0; hl < 2; hl++) {
                    int r  = wm + mt * 16 + group + hl * 8;
                    int qg = q0 + r;
                    bool ok0 = (jgl >= 0) && (jgl <= qg) && (jgl > qg - WIN);
                    bool ok1 = (jgl + 1 >= 0) && (jgl + 1 <= qg) && (jgl + 1 > qg - WIN);
                    float2 o;
                    o.x = ok0 ? acc[mt][nt][hl * 2 + 0] * 0.125f : -1e30f;
                    o.y = ok1 ? acc[mt][nt][hl * 2 + 1] * 0.125f : -1e30f;
                    *(float2*)&Sc[r * SCP + col] = o;
                }
            }
        }
    }
    __syncthreads();

    {
        int r = t >> 2;
        int p = t & 3;
        float mx = -1e30f;
        for (int jj = p * 48; jj < p * 48 + 48; jj++)
            mx = fmaxf(mx, Sc[r * SCP + jj]);
        mx = fmaxf(mx, __shfl_xor_sync(0xFFFFFFFFu, mx, 1));
        mx = fmaxf(mx, __shfl_xor_sync(0xFFFFFFFFu, mx, 2));
        float sum = 0.0f;
        for (int jj = p * 48; jj < p * 48 + 48; jj++) {
            float e = __expf(Sc[r * SCP + jj] - mx);
            Sc[r * SCP + jj] = e;
            sum += e;
        }
        sum += __shfl_xor_sync(0xFFFFFFFFu, sum, 1);
        sum += __shfl_xor_sync(0xFFFFFFFFu, sum, 2);
        float inv = 1.0f / sum;
        for (int jj = p * 48; jj < p * 48 + 48; jj++)
            Sc[r * SCP + jj] = round_tf32(Sc[r * SCP + jj] * inv);
    }
    __syncthreads();

    {
        const int wm = (warp >> 2) * 32;
        const int wn = (warp & 3) * 16;
        float acc[2][2][4];
#pragma unroll
        for (int mt = 0; mt < 2; mt++)
#pragma unroll
            for (int nt = 0; nt < 2; nt++)
#pragma unroll
                for (int j = 0; j < 4; j++) acc[mt][nt][j] = 0.0f;

        for (int c = 0; c < 3; c++) {
            if (c < 2) { CP_WAIT1(); }
            else       { CP_WAIT0(); }
            __syncthreads();
            const float* Vv = sm + ((c & 1) ? OFF_V1 : 0);

#pragma unroll
            for (int kk = 0; kk < 8; kk++) {
                const int k8 = kk * 8;
                uint32_t a[2][4], bf[2][2];
#pragma unroll
                for (int mt = 0; mt < 2; mt++) {
                    int r = wm + mt * 16 + group;
                    int scol = c * 64 + k8 + tig;
                    a[mt][0] = __float_as_uint(Sc[r * SCP + scol]);
                    a[mt][1] = __float_as_uint(Sc[(r + 8) * SCP + scol]);
                    a[mt][2] = __float_as_uint(Sc[r * SCP + scol + 4]);
                    a[mt][3] = __float_as_uint(Sc[(r + 8) * SCP + scol + 4]);
                }
#pragma unroll
                for (int nt = 0; nt < 2; nt++) {
                    int dcol = wn + nt * 8 + group;
                    bf[nt][0] = __float_as_uint(Vv[(k8 + tig) * VPP + dcol]);
                    bf[nt][1] = __float_as_uint(Vv[(k8 + tig + 4) * VPP + dcol]);
                }
#pragma unroll
                for (int mt = 0; mt < 2; mt++)
#pragma unroll
                    for (int nt = 0; nt < 2; nt++)
                        MMA_TF32(acc[mt][nt], a[mt], bf[nt]);
            }

            if (c == 0) {
                __syncthreads();
                issue_V(2, 0);
            }
        }

#pragma unroll
        for (int mt = 0; mt < 2; mt++) {
#pragma unroll
            for (int nt = 0; nt < 2; nt++) {
                int col = wn + nt * 8 + tig * 2;
#pragma unroll
                for (int hl = 0; hl < 2; hl++) {
                    int r = wm + mt * 16 + group + hl * 8;
                    float2 o;
                    o.x = round_tf32(acc[mt][nt][hl * 2 + 0]);
                    o.y = round_tf32(acc[mt][nt][hl * 2 + 1]);
                    *(float2*)&Zh[(size_t)(q0 + r) * 64 + col] = o;
                }
            }
        }
    }
}

// ---------------------------------------------------------------------------
extern "C" void kernel_launch(void* const* d_in, const int* in_sizes, int n_in,
                              void* d_out, int out_size)
{
    const float* qin = (const float*)d_in[0];
    const float* kin = (const float*)d_in[1];
    const float* vin = (const float*)d_in[2];
    const float* WQ  = (const float*)d_in[3];
    const float* WK  = (const float*)d_in[4];
    const float* WV  = (const float*)d_in[5];
    const float* WO  = (const float*)d_in[6];
    const float* bQ  = (const float*)d_in[7];
    const float* bK  = (const float*)d_in[8];
    const float* bV  = (const float*)d_in[9];
    const float* bO  = (const float*)d_in[10];
    float* out = (float*)d_out;

    float *pQ, *pK, *pV, *pZ;
    float *pAq, *pAk, *pAv, *pWq, *pWk, *pWv, *pWo;
    float2* pT;
    cudaGetSymbolAddress((void**)&pQ, g_Q);
    cudaGetSymbolAddress((void**)&pK, g_K);
    cudaGetSymbolAddress((void**)&pV, g_V);
    cudaGetSymbolAddress((void**)&pZ, g_Z);
    cudaGetSymbolAddress((void**)&pAq, g_Aq);
    cudaGetSymbolAddress((void**)&pAk, g_Ak);
    cudaGetSymbolAddress((void**)&pAv, g_Av);
    cudaGetSymbolAddress((void**)&pWq, g_Wq);
    cudaGetSymbolAddress((void**)&pWk, g_Wk);
    cudaGetSymbolAddress((void**)&pWv, g_Wv);
    cudaGetSymbolAddress((void**)&pWo, g_Wo);
    cudaGetSymbolAddress((void**)&pT, g_T);

    const int M = Bb * Ss;       // 4096
    const int N = Hh * DHd;      // 768
    const int Kd = Dd;           // 768

    cudaFuncSetAttribute(tgemm_k,
                         cudaFuncAttributeMaxDynamicSharedMemorySize, GEMM_SMEM);
    cudaFuncSetAttribute(tgemm64_k,
                         cudaFuncAttributeMaxDynamicSharedMemorySize, GEMM64_SMEM);
    cudaFuncSetAttribute(attn_k,
                         cudaFuncAttributeMaxDynamicSharedMemorySize, ATTN_SMEM);

    // Fused init: pre-round operands + rotary table
    init_k<<<11776, 256>>>(qin, kin, vin, WQ, WK, WV, WO,
                           pAq, pAk, pAv, pWq, pWk, pWv, pWo, pT);

    // Fused QKV projections (C head-major; V output pre-rounded: round_z=2)
    tgemm_k<<<dim3(N / 128, M / 128, 3), 256, GEMM_SMEM>>>(
        pAq, pAk, pAv, pWq, pWk, pWv, bQ, bK, bV, pQ, pK, pV, M, N, Kd, 2);

    // Attention (head-major; rotary fused; V double-buffered cp.async)
    attn_k<<<dim3(Ss / 64, Hh, Bb), 256, ATTN_SMEM>>>(pQ, pK, pV, pT, pZ);

    // Output projection: BN=64, 3 CTAs/SM, single wave (384 blocks)
    tgemm64_k<<<dim3(N / 64, M / 128), 256, GEMM64_SMEM>>>(
        pZ, pWo, bO, out, M, N, Kd);
}